// round 8
// baseline (speedup 1.0000x reference)
#include <cuda_runtime.h>
#include <math.h>

#define BATCH 2048
#define FDIM  1024
#define HDIM  1024
#define CDIM  64
#define MDIM  200
#define NITER 20
#define SIGMA 0.1f
#define EPSQP 1e-4f
#define BNEPS 1e-5f
#define CLAMP_BIG 1e30f

// ---------------- scratch (device globals: no allocation allowed) ----------------
__device__ float g_y1[BATCH * HDIM];   // relu(x@W1^T+b1), pre-BN
__device__ float g_pp[BATCH * CDIM];   // relu(h1@W2^T+b2), pre-BN
__device__ float g_a1[HDIM];
__device__ float g_c1[HDIM];
__device__ float g_a2[CDIM];
__device__ float g_c2[CDIM];
__device__ float g_Q[CDIM * CDIM];
__device__ float g_h[MDIM];

// ---------------- f32x2 packed helpers (Blackwell sm_100+) ----------------
typedef unsigned long long ull;
__device__ __forceinline__ ull f2dup(float s) {
    ull r; asm("mov.b64 %0, {%1, %1};" : "=l"(r) : "f"(s)); return r;
}
__device__ __forceinline__ ull f2pack(float lo, float hi) {
    ull r; asm("mov.b64 %0, {%1, %2};" : "=l"(r) : "f"(lo), "f"(hi)); return r;
}
__device__ __forceinline__ ull f2mul(ull a, ull b) {
    ull d; asm("mul.rn.f32x2 %0, %1, %2;" : "=l"(d) : "l"(a), "l"(b)); return d;
}
__device__ __forceinline__ ull f2fma(ull a, ull b, ull c) {
    ull d; asm("fma.rn.f32x2 %0, %1, %2, %3;" : "=l"(d) : "l"(a), "l"(b), "l"(c)); return d;
}
__device__ __forceinline__ void f2unpack(ull v, float& lo, float& hi) {
    asm("mov.b64 {%0, %1}, %2;" : "=f"(lo), "=f"(hi) : "l"(v));
}

// ---------------- prep: Q = tril(L)tril(L)^T + eps I ; h = G z0 + s0 ----------------
__global__ void prep_kernel(const float* __restrict__ L, const float* __restrict__ G,
                            const float* __restrict__ z0, const float* __restrict__ s0)
{
    int t = threadIdx.x;
    for (int idx = t; idx < CDIM * CDIM; idx += 256) {
        int i = idx >> 6, j = idx & 63;
        int km = i < j ? i : j;
        float acc = (i == j) ? EPSQP : 0.f;
        for (int k = 0; k <= km; k++) acc += L[i * CDIM + k] * L[j * CDIM + k];
        g_Q[idx] = acc;
    }
    for (int m = t; m < MDIM; m += 256) {
        float acc = s0[m];
        for (int i = 0; i < CDIM; i++) acc += G[m * CDIM + i] * z0[i];
        g_h[m] = acc;
    }
}

// ---------------- GEMM1: y1 = relu(x @ W1^T + b1)  [2048,1024] ----------------
__global__ void __launch_bounds__(256) gemm1_kernel(const float* __restrict__ x,
                                                    const float* __restrict__ W1,
                                                    const float* __restrict__ b1)
{
    __shared__ float As[16][64];
    __shared__ float Bs[16][64];
    int tid = threadIdx.x;
    int hb = blockIdx.x * 64, rb = blockIdx.y * 64;
    int lr = tid >> 2, lk = (tid & 3) << 2;
    int ty = tid >> 4, tx = tid & 15;
    float acc[4][4];
#pragma unroll
    for (int u = 0; u < 4; u++)
#pragma unroll
        for (int v = 0; v < 4; v++) acc[u][v] = 0.f;

    const float* xp = x + (size_t)(rb + lr) * FDIM + lk;
    const float* wp = W1 + (size_t)(hb + lr) * FDIM + lk;

    for (int k0 = 0; k0 < FDIM; k0 += 16) {
        float4 av = *(const float4*)(xp + k0);
        float4 bv = *(const float4*)(wp + k0);
        As[lk + 0][lr] = av.x; As[lk + 1][lr] = av.y; As[lk + 2][lr] = av.z; As[lk + 3][lr] = av.w;
        Bs[lk + 0][lr] = bv.x; Bs[lk + 1][lr] = bv.y; Bs[lk + 2][lr] = bv.z; Bs[lk + 3][lr] = bv.w;
        __syncthreads();
#pragma unroll
        for (int k = 0; k < 16; k++) {
            float4 a4 = *(const float4*)&As[k][ty << 2];
            float4 b4 = *(const float4*)&Bs[k][tx << 2];
            float a_[4] = {a4.x, a4.y, a4.z, a4.w};
            float b_[4] = {b4.x, b4.y, b4.z, b4.w};
#pragma unroll
            for (int u = 0; u < 4; u++)
#pragma unroll
                for (int v = 0; v < 4; v++) acc[u][v] += a_[u] * b_[v];
        }
        __syncthreads();
    }
#pragma unroll
    for (int u = 0; u < 4; u++) {
        int r = rb + (ty << 2) + u;
        int h = hb + (tx << 2);
        float4 o;
        o.x = fmaxf(acc[u][0] + b1[h + 0], 0.f);
        o.y = fmaxf(acc[u][1] + b1[h + 1], 0.f);
        o.z = fmaxf(acc[u][2] + b1[h + 2], 0.f);
        o.w = fmaxf(acc[u][3] + b1[h + 3], 0.f);
        *(float4*)&g_y1[(size_t)r * HDIM + h] = o;
    }
}

// ---------------- BN1 stats -> fold into a1,c1 (h1 = y1*a1 + c1) ----------------
__global__ void bn1_stats_kernel(const float* __restrict__ gamma, const float* __restrict__ beta)
{
    __shared__ float s1[256], s2[256];
    int tid = threadIdx.x;
    int colBase = blockIdx.x * 64;
    int col = colBase + (tid & 63);
    int rs = tid >> 6;
    float sum = 0.f, sq = 0.f;
    for (int r = rs; r < BATCH; r += 4) {
        float v = g_y1[(size_t)r * HDIM + col];
        sum += v; sq += v * v;
    }
    s1[tid] = sum; s2[tid] = sq;
    __syncthreads();
    if (tid < 64) {
        float S = s1[tid] + s1[tid + 64] + s1[tid + 128] + s1[tid + 192];
        float P = s2[tid] + s2[tid + 64] + s2[tid + 128] + s2[tid + 192];
        float mean = S * (1.f / BATCH);
        float var = P * (1.f / BATCH) - mean * mean;
        float a = gamma[colBase + tid] / sqrtf(var + BNEPS);
        g_a1[colBase + tid] = a;
        g_c1[colBase + tid] = beta[colBase + tid] - mean * a;
    }
}

// ---------------- GEMM2: pp = relu(bn1(y1) @ W2^T + b2)  [2048,64] ----------------
__global__ void __launch_bounds__(256) gemm2_kernel(const float* __restrict__ W2,
                                                    const float* __restrict__ b2)
{
    __shared__ float As[16][64];
    __shared__ float Bs[16][64];
    __shared__ float a1s[HDIM];
    __shared__ float c1s[HDIM];
    int tid = threadIdx.x;
    for (int i = tid; i < HDIM; i += 256) { a1s[i] = g_a1[i]; c1s[i] = g_c1[i]; }
    __syncthreads();

    int rb = blockIdx.x * 64;
    int lr = tid >> 2, lk = (tid & 3) << 2;
    int ty = tid >> 4, tx = tid & 15;
    float acc[4][4];
#pragma unroll
    for (int u = 0; u < 4; u++)
#pragma unroll
        for (int v = 0; v < 4; v++) acc[u][v] = 0.f;

    const float* yp = g_y1 + (size_t)(rb + lr) * HDIM + lk;
    const float* wp = W2 + (size_t)lr * HDIM + lk;

    for (int k0 = 0; k0 < HDIM; k0 += 16) {
        float4 av = *(const float4*)(yp + k0);
        float4 bv = *(const float4*)(wp + k0);
        As[lk + 0][lr] = av.x * a1s[k0 + lk + 0] + c1s[k0 + lk + 0];
        As[lk + 1][lr] = av.y * a1s[k0 + lk + 1] + c1s[k0 + lk + 1];
        As[lk + 2][lr] = av.z * a1s[k0 + lk + 2] + c1s[k0 + lk + 2];
        As[lk + 3][lr] = av.w * a1s[k0 + lk + 3] + c1s[k0 + lk + 3];
        Bs[lk + 0][lr] = bv.x; Bs[lk + 1][lr] = bv.y; Bs[lk + 2][lr] = bv.z; Bs[lk + 3][lr] = bv.w;
        __syncthreads();
#pragma unroll
        for (int k = 0; k < 16; k++) {
            float4 a4 = *(const float4*)&As[k][ty << 2];
            float4 b4 = *(const float4*)&Bs[k][tx << 2];
            float a_[4] = {a4.x, a4.y, a4.z, a4.w};
            float b_[4] = {b4.x, b4.y, b4.z, b4.w};
#pragma unroll
            for (int u = 0; u < 4; u++)
#pragma unroll
                for (int v = 0; v < 4; v++) acc[u][v] += a_[u] * b_[v];
        }
        __syncthreads();
    }
#pragma unroll
    for (int u = 0; u < 4; u++) {
        int r = rb + (ty << 2) + u;
        int n = tx << 2;
        float4 o;
        o.x = fmaxf(acc[u][0] + b2[n + 0], 0.f);
        o.y = fmaxf(acc[u][1] + b2[n + 1], 0.f);
        o.z = fmaxf(acc[u][2] + b2[n + 2], 0.f);
        o.w = fmaxf(acc[u][3] + b2[n + 3], 0.f);
        *(float4*)&g_pp[(size_t)r * CDIM + n] = o;
    }
}

// ---------------- BN2 stats -> a2,c2 ----------------
__global__ void bn2_stats_kernel(const float* __restrict__ gamma, const float* __restrict__ beta)
{
    __shared__ float s1[256], s2[256];
    int tid = threadIdx.x;
    int col = blockIdx.x;
    float sum = 0.f, sq = 0.f;
    for (int r = tid; r < BATCH; r += 256) {
        float v = g_pp[(size_t)r * CDIM + col];
        sum += v; sq += v * v;
    }
    s1[tid] = sum; s2[tid] = sq;
    __syncthreads();
    for (int s = 128; s > 0; s >>= 1) {
        if (tid < s) { s1[tid] += s1[tid + s]; s2[tid] += s2[tid + s]; }
        __syncthreads();
    }
    if (tid == 0) {
        float mean = s1[0] * (1.f / BATCH);
        float var = s2[0] * (1.f / BATCH) - mean * mean;
        float a = gamma[col] / sqrtf(var + BNEPS);
        g_a2[col] = a;
        g_c2[col] = beta[col] - mean * a;
    }
}

// ---------------- IPM: 2 samples/CTA, f32x2 H-formation + blocked LDL^T ----------------
#define GS 66           // even stride: rows 8-byte aligned, conflict-tolerable
#define LCS 66
#define SH_FLOATS   (MDIM * GS + 200)
#define HALF_FLOATS (4224 + 256 + 256 + 16 + 64 + 64 + 64 + 64 + 64 + 8*200 + 40)
#define SM_FLOATS   (SH_FLOATS + 2 * HALF_FLOATS)

__device__ __forceinline__ float scrub(float v)
{
    return fminf(fmaxf(v, -CLAMP_BIG), CLAMP_BIG);
}

__device__ __forceinline__ float warp_rsum(float v)
{
#pragma unroll
    for (int s = 16; s > 0; s >>= 1) v += __shfl_xor_sync(0xffffffffu, v, s);
    return v;
}
__device__ __forceinline__ float warp_rmin(float v)
{
#pragma unroll
    for (int s = 16; s > 0; s >>= 1) v = fminf(v, __shfl_xor_sync(0xffffffffu, v, s));
    return v;
}
__device__ __forceinline__ float warp_rmax(float v)
{
#pragma unroll
    for (int s = 16; s > 0; s >>= 1) v = fmaxf(v, __shfl_xor_sync(0xffffffffu, v, s));
    return v;
}

// packed 64-dot: acc += sum_i a[i]*b[i], both 8B-aligned
__device__ __forceinline__ float dot64_f2(const float* a, const float* b)
{
    ull acc2 = 0ull;
#pragma unroll 8
    for (int i = 0; i < CDIM; i += 2) {
        float2 x = *(const float2*)(a + i);
        float2 y = *(const float2*)(b + i);
        acc2 = f2fma(f2pack(x.x, x.y), f2pack(y.x, y.y), acc2);
    }
    float lo, hi; f2unpack(acc2, lo, hi);
    return lo + hi;
}

// 4x4 LDL^T of the diagonal tile held in a16 (in-place: a16 becomes X = L*D cols).
// L of this diag block goes ONLY to the staging buffer LbD (local 4x4 indexing)
// plus the read-only-later Lc. Never touches Lb (avoids the phase-P2 race).
__device__ __forceinline__ void diag_ldl(float* a16, int cb, float* LbD,
                                         float* Lc, float* invDall)
{
#pragma unroll
    for (int c = 0; c < 4; c++) {
        float h0 = a16[c * 4 + c];
        float v = h0;
#pragma unroll
        for (int k = 0; k < 4; k++)
            if (k < c) v -= a16[c * 4 + k] * LbD[c * 4 + k];
        float piv = fmaxf(v, 1e-12f * fmaxf(h0, EPSQP));
        float inv = 1.f / piv;
        invDall[cb + c] = inv;
#pragma unroll
        for (int r = 0; r < 4; r++) {
            if (r > c) {
                float x = a16[r * 4 + c];
#pragma unroll
                for (int k = 0; k < 4; k++)
                    if (k < c) x -= a16[r * 4 + k] * LbD[c * 4 + k];
                a16[r * 4 + c] = x;
                float l = x * inv;
                LbD[r * 4 + c] = l;
                Lc[(cb + c) * LCS + (cb + r)] = l;
            }
        }
    }
}

__global__ void __launch_bounds__(512, 2) ipm_kernel(const float* __restrict__ G,
                                                     float* __restrict__ out)
{
    extern __shared__ float sm[];
    float* Gp = sm;                 // [200*66] shared by both halves
    float* hh = Gp + MDIM * GS;     // [200]    shared
    int tid  = threadIdx.x;
    int half = tid >> 8;
    int t    = tid & 255;
    int barid = 1 + half;

    float* ms      = hh + 200 + half * HALF_FLOATS;
    float* Lc      = ms;            // [64*66] L column-major: Lc[col*LCS+row]
    float* Xb      = Lc + 4224;     // [64*4]  current block X (=L*D) rows
    float* Lb      = Xb + 256;      // [64*4]  current block L rows (panel only)
    float* LbD     = Lb + 256;      // [16]    current diag block L (staging)
    float* invDall = LbD + 16;      // [64]
    float* yv      = invDall + 64;  // [64] rhs -> forward-solve y
    float* dzv     = yv + 64;       // [64]
    float* pb      = dzv + 64;      // [64]
    float* zv      = pb + 64;       // [64]
    float* sv      = zv + 64;       // [200]
    float* lv      = sv + 200;
    float* slv     = lv + 200;
    float* dv      = slv + 200;
    float* rpv     = dv + 200;
    float* lwv     = rpv + 200;
    float* dsv     = lwv + 200;
    float* dlv     = dsv + 200;
    float* red     = dlv + 200;     // [40]

#define HBAR() asm volatile("bar.sync %0, %1;" :: "r"(barid), "r"(256) : "memory")

    int b = blockIdx.x * 2 + half;
    int w = t >> 5;
    int lane = t & 31;

    // cooperative load of G (both halves together)
    for (int idx = tid; idx < MDIM * CDIM; idx += 512) {
        int m = idx >> 6, i = idx & 63;
        Gp[m * GS + i] = G[idx];
    }
    if (tid < MDIM) hh[tid] = g_h[tid];
    __syncthreads();

    if (t < MDIM) { sv[t] = 1.f; lv[t] = 1.f; }
    if (t < CDIM) {
        pb[t] = g_a2[t] * g_pp[(size_t)b * CDIM + t] + g_c2[t];
        zv[t] = 0.f;
    }

    // lower-triangle 4x4 tile mapping for t < 136
    int ta = 0, tb = 0;
    if (t < 136) {
        int lin = t, a = 0;
        while (lin > a) { lin -= (a + 1); a++; }
        ta = a; tb = lin;
    }
    int ti = ta << 2, tj = tb << 2;

    HBAR();

    float mu = 0.f;
    for (int iter = 0; iter < NITER; iter++) {
        // --- Phase A: slv, d, rp, mu partials ---
        float cand = 0.f;
        if (t < MDIM) {
            float s_ = sv[t], l_ = lv[t];
            float sl = s_ * l_;
            slv[t] = sl;
            dv[t] = l_ / s_;
            float acc = s_ - hh[t] + dot64_f2(zv, Gp + t * GS);
            rpv[t] = acc;
            cand = sl;
        }
        cand = warp_rsum(cand);
        if (lane == 0) red[w] = cand;
        HBAR();

        // --- Phase B: mu, lam+w ---
        mu = SIGMA * (1.f / MDIM) *
             (red[0] + red[1] + red[2] + red[3] + red[4] + red[5] + red[6] + red[7]);
        if (t < MDIM) {
            float wv = (mu - slv[t] + lv[t] * rpv[t]) / sv[t];
            lwv[t] = lv[t] + wv;
        }
        HBAR();

        // --- Phase CF: H tiles in registers via f32x2 (t<136) || rhs (160<=t<224) ---
        float a16[16];
        if (t < 136) {
            // accA[c] packs rows (ti+0,ti+1) of column tj+c; accB[c] rows (ti+2,ti+3)
            ull accA[4], accB[4];
            {
                float4 q0 = *(const float4*)&g_Q[(ti + 0) * CDIM + tj];
                float4 q1 = *(const float4*)&g_Q[(ti + 1) * CDIM + tj];
                float4 q2 = *(const float4*)&g_Q[(ti + 2) * CDIM + tj];
                float4 q3 = *(const float4*)&g_Q[(ti + 3) * CDIM + tj];
                accA[0] = f2pack(q0.x, q1.x); accA[1] = f2pack(q0.y, q1.y);
                accA[2] = f2pack(q0.z, q1.z); accA[3] = f2pack(q0.w, q1.w);
                accB[0] = f2pack(q2.x, q3.x); accB[1] = f2pack(q2.y, q3.y);
                accB[2] = f2pack(q2.z, q3.z); accB[3] = f2pack(q2.w, q3.w);
            }
#pragma unroll 2
            for (int m = 0; m < MDIM; m++) {
                const float* gr = Gp + m * GS;
                ull dm2 = f2dup(dv[m]);
                float2 fa01 = *(const float2*)(gr + ti);
                float2 fa23 = *(const float2*)(gr + ti + 2);
                float2 fb01 = *(const float2*)(gr + tj);
                float2 fb23 = *(const float2*)(gr + tj + 2);
                ull sa01 = f2mul(f2pack(fa01.x, fa01.y), dm2);  // (d*a0, d*a1)
                ull sa23 = f2mul(f2pack(fa23.x, fa23.y), dm2);  // (d*a2, d*a3)
                ull db0 = f2dup(fb01.x), db1 = f2dup(fb01.y);
                ull db2 = f2dup(fb23.x), db3 = f2dup(fb23.y);
                accA[0] = f2fma(sa01, db0, accA[0]);
                accA[1] = f2fma(sa01, db1, accA[1]);
                accA[2] = f2fma(sa01, db2, accA[2]);
                accA[3] = f2fma(sa01, db3, accA[3]);
                accB[0] = f2fma(sa23, db0, accB[0]);
                accB[1] = f2fma(sa23, db1, accB[1]);
                accB[2] = f2fma(sa23, db2, accB[2]);
                accB[3] = f2fma(sa23, db3, accB[3]);
            }
#pragma unroll
            for (int c = 0; c < 4; c++) {
                f2unpack(accA[c], a16[0 * 4 + c], a16[1 * 4 + c]);
                f2unpack(accB[c], a16[2 * 4 + c], a16[3 * 4 + c]);
            }
            if (t == 0) diag_ldl(a16, 0, LbD, Lc, invDall);   // block 0 diagonal
        } else if (t >= 160 && t < 160 + CDIM) {
            int c = t - 160;
            float acc = pb[c] + dot64_f2(zv, &g_Q[c * CDIM]);
#pragma unroll 4
            for (int m = 0; m < MDIM; m++) acc += lwv[m] * Gp[m * GS + c];
            yv[c] = -acc;    // rhs, becomes forward-solve y in place
        }
        HBAR();

        // --- Blocked LDL^T (4-wide panels) with fused forward solve ---
        for (int jb = 0; jb < 16; jb++) {
            int cb = jb << 2;
            // P1: panel scale (tiles in column jb) + y diag-solve (t==136)
            if (t < 136 && tb == jb && ta > jb) {
#pragma unroll
                for (int c = 0; c < 4; c++) {
                    float inv = invDall[cb + c];
                    float l0 = LbD[c * 4 + 0];
                    float l1 = LbD[c * 4 + 1];
                    float l2 = LbD[c * 4 + 2];
#pragma unroll
                    for (int r = 0; r < 4; r++) {
                        float x = a16[r * 4 + c];
                        if (c > 0) x -= a16[r * 4 + 0] * l0;
                        if (c > 1) x -= a16[r * 4 + 1] * l1;
                        if (c > 2) x -= a16[r * 4 + 2] * l2;
                        a16[r * 4 + c] = x;
                        float l = x * inv;
                        Xb[(ti + r) * 4 + c] = x;
                        Lb[(ti + r) * 4 + c] = l;
                        Lc[(cb + c) * LCS + (ti + r)] = l;
                    }
                }
            } else if (t == 136) {
                // forward solve rows cb..cb+3 (unit diag) using staged diag L
#pragma unroll
                for (int c = 0; c < 4; c++) {
                    float yc = yv[cb + c];
#pragma unroll
                    for (int k = 0; k < 4; k++)
                        if (k < c) yc -= LbD[c * 4 + k] * yv[cb + k];
                    yv[cb + c] = yc;
                }
            }
            HBAR();
            if (jb < 15) {
                // P2: trailing rank-4 update in registers + next diag LDL + y trailing
                if (t < 136 && ta > jb && tb > jb) {
                    const float4* X4 = (const float4*)Xb;
                    const float4* L4 = (const float4*)Lb;
                    float4 xr0 = X4[ti + 0], xr1 = X4[ti + 1],
                           xr2 = X4[ti + 2], xr3 = X4[ti + 3];
                    float4 lc0 = L4[tj + 0], lc1 = L4[tj + 1],
                           lc2 = L4[tj + 2], lc3 = L4[tj + 3];
#define DOT4(p, q) (p.x * q.x + p.y * q.y + p.z * q.z + p.w * q.w)
                    a16[0]  -= DOT4(xr0, lc0); a16[1]  -= DOT4(xr0, lc1);
                    a16[2]  -= DOT4(xr0, lc2); a16[3]  -= DOT4(xr0, lc3);
                    a16[4]  -= DOT4(xr1, lc0); a16[5]  -= DOT4(xr1, lc1);
                    a16[6]  -= DOT4(xr1, lc2); a16[7]  -= DOT4(xr1, lc3);
                    a16[8]  -= DOT4(xr2, lc0); a16[9]  -= DOT4(xr2, lc1);
                    a16[10] -= DOT4(xr2, lc2); a16[11] -= DOT4(xr2, lc3);
                    a16[12] -= DOT4(xr3, lc0); a16[13] -= DOT4(xr3, lc1);
                    a16[14] -= DOT4(xr3, lc2); a16[15] -= DOT4(xr3, lc3);
#undef DOT4
                    if (ta == jb + 1 && tb == jb + 1)
                        diag_ldl(a16, cb + 4, LbD, Lc, invDall);  // writes staging only
                } else if (t >= 137 && t < 137 + (15 - jb)) {
                    int g = jb + 1 + (t - 137);
                    int r0 = g << 2;
                    float y0 = yv[cb + 0], y1 = yv[cb + 1],
                          y2 = yv[cb + 2], y3 = yv[cb + 3];
                    const float4* L4 = (const float4*)Lb;
#pragma unroll
                    for (int r = 0; r < 4; r++) {
                        float4 lr = L4[r0 + r];
                        yv[r0 + r] -= lr.x * y0 + lr.y * y1 + lr.z * y2 + lr.w * y3;
                    }
                }
                HBAR();
            }
        }

        // --- backward solve: warp 0, shfl-serial, zero block barriers ---
        if (w == 0) {
            float w0 = yv[lane] * invDall[lane];
            float w1 = yv[lane + 32] * invDall[lane + 32];
            for (int j = CDIM - 1; j >= 0; j--) {
                float src = (j >= 32) ? w1 : w0;
                float xj = __shfl_sync(0xffffffffu, src, j & 31);
                xj = scrub(xj);
                if (lane == (j & 31)) dzv[j] = xj;
                if (lane < j)      w0 -= Lc[lane * LCS + j] * xj;
                if (lane + 32 < j) w1 -= Lc[(lane + 32) * LCS + j] * xj;
            }
        }
        HBAR();

        // --- Phase I: ds, dlam, alpha candidates ---
        float ac = CLAMP_BIG;
        if (t < MDIM) {
            float acc = -rpv[t] - dot64_f2(dzv, Gp + t * GS);
            acc = scrub(acc);
            dsv[t] = acc;
            float dl = scrub((mu - slv[t] - lv[t] * acc) / sv[t]);
            dlv[t] = dl;
            float x1 = (acc < 0.f) ? (-sv[t] / acc) : CLAMP_BIG;
            float x2 = (dl < 0.f) ? (-lv[t] / dl) : CLAMP_BIG;
            ac = fminf(x1, x2);
        }
        ac = warp_rmin(ac);
        if (lane == 0) red[w] = ac;
        HBAR();

        // --- Phase K: step ---
        float amin = fminf(fminf(fminf(red[0], red[1]), fminf(red[2], red[3])),
                           fminf(fminf(red[4], red[5]), fminf(red[6], red[7])));
        float alpha = 0.99f * fminf(1.f, amin);
        if (t < CDIM) zv[t] += alpha * dzv[t];
        if (t < MDIM) {
            sv[t] = fmaxf(sv[t] + alpha * dsv[t], 1e-30f);
            lv[t] = fmaxf(lv[t] + alpha * dlv[t], 1e-30f);
        }
        HBAR();
    }

    // --- log_softmax over 64 classes ---
    float mz = (t < CDIM) ? zv[t] : -CLAMP_BIG;
    mz = warp_rmax(mz);
    if (lane == 0) red[w] = mz;
    HBAR();
    float zmax = fmaxf(fmaxf(fmaxf(red[0], red[1]), fmaxf(red[2], red[3])),
                       fmaxf(fmaxf(red[4], red[5]), fmaxf(red[6], red[7])));
    float ev = (t < CDIM) ? expf(zv[t] - zmax) : 0.f;
    ev = warp_rsum(ev);
    if (lane == 0) red[8 + w] = ev;
    HBAR();
    float ssum = red[8] + red[9] + red[10] + red[11] +
                 red[12] + red[13] + red[14] + red[15];
    float lse = logf(ssum);
    if (t < CDIM)
        out[(size_t)b * CDIM + t] = zv[t] - zmax - lse;
#undef HBAR
}

// ---------------- launch ----------------
extern "C" void kernel_launch(void* const* d_in, const int* in_sizes, int n_in,
                              void* d_out, int out_size)
{
    const float* x    = (const float*)d_in[0];
    const float* W1   = (const float*)d_in[1];
    const float* b1   = (const float*)d_in[2];
    const float* W2   = (const float*)d_in[3];
    const float* b2   = (const float*)d_in[4];
    const float* bn1g = (const float*)d_in[5];
    const float* bn1b = (const float*)d_in[6];
    const float* bn2g = (const float*)d_in[7];
    const float* bn2b = (const float*)d_in[8];
    const float* L    = (const float*)d_in[9];
    const float* G    = (const float*)d_in[10];
    const float* z0   = (const float*)d_in[11];
    const float* s0   = (const float*)d_in[12];
    float* out = (float*)d_out;

    cudaFuncSetAttribute(ipm_kernel, cudaFuncAttributeMaxDynamicSharedMemorySize,
                         SM_FLOATS * sizeof(float));

    prep_kernel<<<1, 256>>>(L, G, z0, s0);
    gemm1_kernel<<<dim3(HDIM / 64, BATCH / 64), 256>>>(x, W1, b1);
    bn1_stats_kernel<<<HDIM / 64, 256>>>(bn1g, bn1b);
    gemm2_kernel<<<BATCH / 64, 256>>>(W2, b2);
    bn2_stats_kernel<<<CDIM, 256>>>(bn2g, bn2b);
    ipm_kernel<<<BATCH / 2, 512, SM_FLOATS * sizeof(float)>>>(G, out);
}

// round 10
// speedup vs baseline: 1.0013x; 1.0013x over previous
#include <cuda_runtime.h>
#include <math.h>

#define BATCH 2048
#define FDIM  1024
#define HDIM  1024
#define CDIM  64
#define MDIM  200
#define NITER 20
#define SIGMA 0.1f
#define EPSQP 1e-4f
#define BNEPS 1e-5f
#define CLAMP_BIG 1e30f

__device__ float g_y1[BATCH * HDIM];
__device__ float g_pp[BATCH * CDIM];
__device__ float g_a1[HDIM];
__device__ float g_c1[HDIM];
__device__ float g_a2[CDIM];
__device__ float g_c2[CDIM];
__device__ float g_Q[CDIM * CDIM];
__device__ float g_h[MDIM];

typedef unsigned long long ull;
__device__ __forceinline__ ull f2dup(float s) {
    ull r; asm("mov.b64 %0, {%1, %1};" : "=l"(r) : "f"(s)); return r;
}
__device__ __forceinline__ ull f2pack(float lo, float hi) {
    ull r; asm("mov.b64 %0, {%1, %2};" : "=l"(r) : "f"(lo), "f"(hi)); return r;
}
__device__ __forceinline__ ull f2mul(ull a, ull b) {
    ull d; asm("mul.rn.f32x2 %0, %1, %2;" : "=l"(d) : "l"(a), "l"(b)); return d;
}
__device__ __forceinline__ ull f2fma(ull a, ull b, ull c) {
    ull d; asm("fma.rn.f32x2 %0, %1, %2, %3;" : "=l"(d) : "l"(a), "l"(b), "l"(c)); return d;
}
__device__ __forceinline__ void f2unpack(ull v, float& lo, float& hi) {
    asm("mov.b64 {%0, %1}, %2;" : "=f"(lo), "=f"(hi) : "l"(v));
}

__global__ void prep_kernel(const float* __restrict__ L, const float* __restrict__ G,
                            const float* __restrict__ z0, const float* __restrict__ s0)
{
    int t = threadIdx.x;
    for (int idx = t; idx < CDIM * CDIM; idx += 256) {
        int i = idx >> 6, j = idx & 63;
        int km = i < j ? i : j;
        float acc = (i == j) ? EPSQP : 0.f;
        for (int k = 0; k <= km; k++) acc += L[i * CDIM + k] * L[j * CDIM + k];
        g_Q[idx] = acc;
    }
    for (int m = t; m < MDIM; m += 256) {
        float acc = s0[m];
        for (int i = 0; i < CDIM; i++) acc += G[m * CDIM + i] * z0[i];
        g_h[m] = acc;
    }
}

__global__ void __launch_bounds__(256) gemm1_kernel(const float* __restrict__ x,
                                                    const float* __restrict__ W1,
                                                    const float* __restrict__ b1)
{
    __shared__ float As[16][64];
    __shared__ float Bs[16][64];
    int tid = threadIdx.x;
    int hb = blockIdx.x * 64, rb = blockIdx.y * 64;
    int lr = tid >> 2, lk = (tid & 3) << 2;
    int ty = tid >> 4, tx = tid & 15;
    float acc[4][4];
#pragma unroll
    for (int u = 0; u < 4; u++)
#pragma unroll
        for (int v = 0; v < 4; v++) acc[u][v] = 0.f;

    const float* xp = x + (size_t)(rb + lr) * FDIM + lk;
    const float* wp = W1 + (size_t)(hb + lr) * FDIM + lk;

    for (int k0 = 0; k0 < FDIM; k0 += 16) {
        float4 av = *(const float4*)(xp + k0);
        float4 bv = *(const float4*)(wp + k0);
        As[lk + 0][lr] = av.x; As[lk + 1][lr] = av.y; As[lk + 2][lr] = av.z; As[lk + 3][lr] = av.w;
        Bs[lk + 0][lr] = bv.x; Bs[lk + 1][lr] = bv.y; Bs[lk + 2][lr] = bv.z; Bs[lk + 3][lr] = bv.w;
        __syncthreads();
#pragma unroll
        for (int k = 0; k < 16; k++) {
            float4 a4 = *(const float4*)&As[k][ty << 2];
            float4 b4 = *(const float4*)&Bs[k][tx << 2];
            float a_[4] = {a4.x, a4.y, a4.z, a4.w};
            float b_[4] = {b4.x, b4.y, b4.z, b4.w};
#pragma unroll
            for (int u = 0; u < 4; u++)
#pragma unroll
                for (int v = 0; v < 4; v++) acc[u][v] += a_[u] * b_[v];
        }
        __syncthreads();
    }
#pragma unroll
    for (int u = 0; u < 4; u++) {
        int r = rb + (ty << 2) + u;
        int h = hb + (tx << 2);
        float4 o;
        o.x = fmaxf(acc[u][0] + b1[h + 0], 0.f);
        o.y = fmaxf(acc[u][1] + b1[h + 1], 0.f);
        o.z = fmaxf(acc[u][2] + b1[h + 2], 0.f);
        o.w = fmaxf(acc[u][3] + b1[h + 3], 0.f);
        *(float4*)&g_y1[(size_t)r * HDIM + h] = o;
    }
}

__global__ void bn1_stats_kernel(const float* __restrict__ gamma, const float* __restrict__ beta)
{
    __shared__ float s1[256], s2[256];
    int tid = threadIdx.x;
    int colBase = blockIdx.x * 64;
    int col = colBase + (tid & 63);
    int rs = tid >> 6;
    float sum = 0.f, sq = 0.f;
    for (int r = rs; r < BATCH; r += 4) {
        float v = g_y1[(size_t)r * HDIM + col];
        sum += v; sq += v * v;
    }
    s1[tid] = sum; s2[tid] = sq;
    __syncthreads();
    if (tid < 64) {
        float S = s1[tid] + s1[tid + 64] + s1[tid + 128] + s1[tid + 192];
        float P = s2[tid] + s2[tid + 64] + s2[tid + 128] + s2[tid + 192];
        float mean = S * (1.f / BATCH);
        float var = P * (1.f / BATCH) - mean * mean;
        float a = gamma[colBase + tid] / sqrtf(var + BNEPS);
        g_a1[colBase + tid] = a;
        g_c1[colBase + tid] = beta[colBase + tid] - mean * a;
    }
}

__global__ void __launch_bounds__(256) gemm2_kernel(const float* __restrict__ W2,
                                                    const float* __restrict__ b2)
{
    __shared__ float As[16][64];
    __shared__ float Bs[16][64];
    __shared__ float a1s[HDIM];
    __shared__ float c1s[HDIM];
    int tid = threadIdx.x;
    for (int i = tid; i < HDIM; i += 256) { a1s[i] = g_a1[i]; c1s[i] = g_c1[i]; }
    __syncthreads();

    int rb = blockIdx.x * 64;
    int lr = tid >> 2, lk = (tid & 3) << 2;
    int ty = tid >> 4, tx = tid & 15;
    float acc[4][4];
#pragma unroll
    for (int u = 0; u < 4; u++)
#pragma unroll
        for (int v = 0; v < 4; v++) acc[u][v] = 0.f;

    const float* yp = g_y1 + (size_t)(rb + lr) * HDIM + lk;
    const float* wp = W2 + (size_t)lr * HDIM + lk;

    for (int k0 = 0; k0 < HDIM; k0 += 16) {
        float4 av = *(const float4*)(yp + k0);
        float4 bv = *(const float4*)(wp + k0);
        As[lk + 0][lr] = av.x * a1s[k0 + lk + 0] + c1s[k0 + lk + 0];
        As[lk + 1][lr] = av.y * a1s[k0 + lk + 1] + c1s[k0 + lk + 1];
        As[lk + 2][lr] = av.z * a1s[k0 + lk + 2] + c1s[k0 + lk + 2];
        As[lk + 3][lr] = av.w * a1s[k0 + lk + 3] + c1s[k0 + lk + 3];
        Bs[lk + 0][lr] = bv.x; Bs[lk + 1][lr] = bv.y; Bs[lk + 2][lr] = bv.z; Bs[lk + 3][lr] = bv.w;
        __syncthreads();
#pragma unroll
        for (int k = 0; k < 16; k++) {
            float4 a4 = *(const float4*)&As[k][ty << 2];
            float4 b4 = *(const float4*)&Bs[k][tx << 2];
            float a_[4] = {a4.x, a4.y, a4.z, a4.w};
            float b_[4] = {b4.x, b4.y, b4.z, b4.w};
#pragma unroll
            for (int u = 0; u < 4; u++)
#pragma unroll
                for (int v = 0; v < 4; v++) acc[u][v] += a_[u] * b_[v];
        }
        __syncthreads();
    }
#pragma unroll
    for (int u = 0; u < 4; u++) {
        int r = rb + (ty << 2) + u;
        int n = tx << 2;
        float4 o;
        o.x = fmaxf(acc[u][0] + b2[n + 0], 0.f);
        o.y = fmaxf(acc[u][1] + b2[n + 1], 0.f);
        o.z = fmaxf(acc[u][2] + b2[n + 2], 0.f);
        o.w = fmaxf(acc[u][3] + b2[n + 3], 0.f);
        *(float4*)&g_pp[(size_t)r * CDIM + n] = o;
    }
}

__global__ void bn2_stats_kernel(const float* __restrict__ gamma, const float* __restrict__ beta)
{
    __shared__ float s1[256], s2[256];
    int tid = threadIdx.x;
    int col = blockIdx.x;
    float sum = 0.f, sq = 0.f;
    for (int r = tid; r < BATCH; r += 256) {
        float v = g_pp[(size_t)r * CDIM + col];
        sum += v; sq += v * v;
    }
    s1[tid] = sum; s2[tid] = sq;
    __syncthreads();
    for (int s = 128; s > 0; s >>= 1) {
        if (tid < s) { s1[tid] += s1[tid + s]; s2[tid] += s2[tid + s]; }
        __syncthreads();
    }
    if (tid == 0) {
        float mean = s1[0] * (1.f / BATCH);
        float var = s2[0] * (1.f / BATCH) - mean * mean;
        float a = gamma[col] / sqrtf(var + BNEPS);
        g_a2[col] = a;
        g_c2[col] = beta[col] - mean * a;
    }
}

// ---------------- IPM ----------------
#define GS 66
#define LCS 66
#define SH_FLOATS   (MDIM * GS + 200)
// Lc 4224 + Xb 256 + Lb 256 + LbD 16 + invDall/yv/dzv/pb/zv (5*64) + dv/lwv (2*200) + red 40
#define HALF_FLOATS (4224 + 256 + 256 + 16 + 5*64 + 2*200 + 40)
#define SM_FLOATS   (SH_FLOATS + 2 * HALF_FLOATS)

__device__ __forceinline__ float scrub(float v)
{
    return fminf(fmaxf(v, -CLAMP_BIG), CLAMP_BIG);
}
__device__ __forceinline__ float warp_rsum(float v)
{
#pragma unroll
    for (int s = 16; s > 0; s >>= 1) v += __shfl_xor_sync(0xffffffffu, v, s);
    return v;
}
__device__ __forceinline__ float warp_rmin(float v)
{
#pragma unroll
    for (int s = 16; s > 0; s >>= 1) v = fminf(v, __shfl_xor_sync(0xffffffffu, v, s));
    return v;
}
__device__ __forceinline__ float warp_rmax(float v)
{
#pragma unroll
    for (int s = 16; s > 0; s >>= 1) v = fmaxf(v, __shfl_xor_sync(0xffffffffu, v, s));
    return v;
}
__device__ __forceinline__ float dot64_f2(const float* a, const float* b)
{
    ull acc2 = 0ull;
#pragma unroll 8
    for (int i = 0; i < CDIM; i += 2) {
        float2 x = *(const float2*)(a + i);
        float2 y = *(const float2*)(b + i);
        acc2 = f2fma(f2pack(x.x, x.y), f2pack(y.x, y.y), acc2);
    }
    float lo, hi; f2unpack(acc2, lo, hi);
    return lo + hi;
}
__device__ __forceinline__ float min8(const float* red)
{
    return fminf(fminf(fminf(red[0], red[1]), fminf(red[2], red[3])),
                 fminf(fminf(red[4], red[5]), fminf(red[6], red[7])));
}

__device__ __forceinline__ void diag_ldl(float* a16, int cb, float* LbD,
                                         float* Lc, float* invDall)
{
#pragma unroll
    for (int c = 0; c < 4; c++) {
        float h0 = a16[c * 4 + c];
        float v = h0;
#pragma unroll
        for (int k = 0; k < 4; k++)
            if (k < c) v -= a16[c * 4 + k] * LbD[c * 4 + k];
        float piv = fmaxf(v, 1e-12f * fmaxf(h0, EPSQP));
        float inv = 1.f / piv;
        invDall[cb + c] = inv;
#pragma unroll
        for (int r = 0; r < 4; r++) {
            if (r > c) {
                float x = a16[r * 4 + c];
#pragma unroll
                for (int k = 0; k < 4; k++)
                    if (k < c) x -= a16[r * 4 + k] * LbD[c * 4 + k];
                a16[r * 4 + c] = x;
                float l = x * inv;
                LbD[r * 4 + c] = l;
                Lc[(cb + c) * LCS + (cb + r)] = l;
            }
        }
    }
}

__global__ void __launch_bounds__(512, 2) ipm_kernel(const float* __restrict__ G,
                                                     float* __restrict__ out)
{
    extern __shared__ float sm[];
    float* Gp = sm;
    float* hh = Gp + MDIM * GS;
    int tid  = threadIdx.x;
    int half = tid >> 8;
    int t    = tid & 255;
    int barid = 1 + half;

    float* ms      = hh + 200 + half * HALF_FLOATS;
    float* Lc      = ms;            // [64*66]
    float* Xb      = Lc + 4224;     // [64*4]
    float* Lb      = Xb + 256;      // [64*4]
    float* LbD     = Lb + 256;      // [16]
    float* invDall = LbD + 16;      // [64]
    float* yv      = invDall + 64;  // [64]
    float* dzv     = yv + 64;       // [64]
    float* pb      = dzv + 64;      // [64]
    float* zv      = pb + 64;       // [64]
    float* dv      = zv + 64;       // [200]
    float* lwv     = dv + 200;      // [200]
    float* red     = lwv + 200;     // [40]  0..7 mu, 16..23 alpha, 0..15 softmax

#define HBAR() asm volatile("bar.sync %0, %1;" :: "r"(barid), "r"(256) : "memory")

    int b = blockIdx.x * 2 + half;
    int w = t >> 5;
    int lane = t & 31;

    for (int idx = tid; idx < MDIM * CDIM; idx += 512) {
        int m = idx >> 6, i = idx & 63;
        Gp[m * GS + i] = G[idx];
    }
    if (tid < MDIM) hh[tid] = g_h[tid];
    __syncthreads();

    // per-m state in registers of thread t (t < MDIM)
    float s_ = 1.f, l_ = 1.f, sl_ = 1.f;
    float rp_ = (t < MDIM) ? (1.f - hh[t]) : 0.f;   // rp0 = s0 - h (z0 = 0)
    float ds_ = 0.f, dl_ = 0.f;

    if (t < CDIM) {
        pb[t] = g_a2[t] * g_pp[(size_t)b * CDIM + t] + g_c2[t];
        zv[t] = 0.f;
    }

    int ta = 0, tb = 0;
    if (t < 136) {
        int lin = t, a = 0;
        while (lin > a) { lin -= (a + 1); a++; }
        ta = a; tb = lin;
    }
    int ti = ta << 2, tj = tb << 2;

    HBAR();

    float mu = 0.f;
    for (int iter = 0; iter < NITER; iter++) {
        // --- top phase: apply previous step + slv/dv/mu partials ---
        if (iter > 0) {
            float alpha = 0.99f * fminf(1.f, min8(red + 16));
            if (t < MDIM) {
                s_ = fmaxf(s_ + alpha * ds_, 1e-30f);
                l_ = fmaxf(l_ + alpha * dl_, 1e-30f);
                rp_ *= (1.f - alpha);
            }
            if (t < CDIM) zv[t] += alpha * dzv[t];
        }
        float cand = 0.f;
        if (t < MDIM) {
            sl_ = s_ * l_;
            dv[t] = l_ / s_;
            cand = sl_;
        }
        cand = warp_rsum(cand);
        if (lane == 0) red[w] = cand;
        HBAR();

        // --- B: mu, lam+w ---
        mu = SIGMA * (1.f / MDIM) *
             (red[0] + red[1] + red[2] + red[3] + red[4] + red[5] + red[6] + red[7]);
        if (t < MDIM) {
            float wv = (mu - sl_ + l_ * rp_) / s_;
            lwv[t] = l_ + wv;
        }
        HBAR();

        // --- CF: H tiles in registers via f32x2 (t<136) || rhs (160<=t<224) ---
        float a16[16];
        if (t < 136) {
            ull accA[4], accB[4];
            {
                float4 q0 = *(const float4*)&g_Q[(ti + 0) * CDIM + tj];
                float4 q1 = *(const float4*)&g_Q[(ti + 1) * CDIM + tj];
                float4 q2 = *(const float4*)&g_Q[(ti + 2) * CDIM + tj];
                float4 q3 = *(const float4*)&g_Q[(ti + 3) * CDIM + tj];
                accA[0] = f2pack(q0.x, q1.x); accA[1] = f2pack(q0.y, q1.y);
                accA[2] = f2pack(q0.z, q1.z); accA[3] = f2pack(q0.w, q1.w);
                accB[0] = f2pack(q2.x, q3.x); accB[1] = f2pack(q2.y, q3.y);
                accB[2] = f2pack(q2.z, q3.z); accB[3] = f2pack(q2.w, q3.w);
            }
#pragma unroll 2
            for (int m = 0; m < MDIM; m++) {
                const float* gr = Gp + m * GS;
                ull dm2 = f2dup(dv[m]);
                float2 fa01 = *(const float2*)(gr + ti);
                float2 fa23 = *(const float2*)(gr + ti + 2);
                float2 fb01 = *(const float2*)(gr + tj);
                float2 fb23 = *(const float2*)(gr + tj + 2);
                ull sa01 = f2mul(f2pack(fa01.x, fa01.y), dm2);
                ull sa23 = f2mul(f2pack(fa23.x, fa23.y), dm2);
                ull db0 = f2dup(fb01.x), db1 = f2dup(fb01.y);
                ull db2 = f2dup(fb23.x), db3 = f2dup(fb23.y);
                accA[0] = f2fma(sa01, db0, accA[0]);
                accA[1] = f2fma(sa01, db1, accA[1]);
                accA[2] = f2fma(sa01, db2, accA[2]);
                accA[3] = f2fma(sa01, db3, accA[3]);
                accB[0] = f2fma(sa23, db0, accB[0]);
                accB[1] = f2fma(sa23, db1, accB[1]);
                accB[2] = f2fma(sa23, db2, accB[2]);
                accB[3] = f2fma(sa23, db3, accB[3]);
            }
#pragma unroll
            for (int c = 0; c < 4; c++) {
                f2unpack(accA[c], a16[0 * 4 + c], a16[1 * 4 + c]);
                f2unpack(accB[c], a16[2 * 4 + c], a16[3 * 4 + c]);
            }
            if (t == 0) diag_ldl(a16, 0, LbD, Lc, invDall);
        } else if (t >= 160 && t < 160 + CDIM) {
            int c = t - 160;
            float acc = pb[c] + dot64_f2(zv, &g_Q[c * CDIM]);
#pragma unroll 4
            for (int m = 0; m < MDIM; m++) acc += lwv[m] * Gp[m * GS + c];
            yv[c] = -acc;
        }
        HBAR();

        // --- blocked LDL^T (4-wide) + fused forward solve ---
        for (int jb = 0; jb < 16; jb++) {
            int cb = jb << 2;
            if (t < 136 && tb == jb && ta > jb) {
#pragma unroll
                for (int c = 0; c < 4; c++) {
                    float inv = invDall[cb + c];
                    float l0 = LbD[c * 4 + 0];
                    float l1 = LbD[c * 4 + 1];
                    float l2 = LbD[c * 4 + 2];
#pragma unroll
                    for (int r = 0; r < 4; r++) {
                        float x = a16[r * 4 + c];
                        if (c > 0) x -= a16[r * 4 + 0] * l0;
                        if (c > 1) x -= a16[r * 4 + 1] * l1;
                        if (c > 2) x -= a16[r * 4 + 2] * l2;
                        a16[r * 4 + c] = x;
                        float l = x * inv;
                        Xb[(ti + r) * 4 + c] = x;
                        Lb[(ti + r) * 4 + c] = l;
                        Lc[(cb + c) * LCS + (ti + r)] = l;
                    }
                }
            } else if (t == 136) {
#pragma unroll
                for (int c = 0; c < 4; c++) {
                    float yc = yv[cb + c];
#pragma unroll
                    for (int k = 0; k < 4; k++)
                        if (k < c) yc -= LbD[c * 4 + k] * yv[cb + k];
                    yv[cb + c] = yc;
                }
            }
            HBAR();
            if (jb < 15) {
                if (t < 136 && ta > jb && tb > jb) {
                    const float4* X4 = (const float4*)Xb;
                    const float4* L4 = (const float4*)Lb;
                    float4 xr0 = X4[ti + 0], xr1 = X4[ti + 1],
                           xr2 = X4[ti + 2], xr3 = X4[ti + 3];
                    float4 lc0 = L4[tj + 0], lc1 = L4[tj + 1],
                           lc2 = L4[tj + 2], lc3 = L4[tj + 3];
#define DOT4(p, q) (p.x * q.x + p.y * q.y + p.z * q.z + p.w * q.w)
                    a16[0]  -= DOT4(xr0, lc0); a16[1]  -= DOT4(xr0, lc1);
                    a16[2]  -= DOT4(xr0, lc2); a16[3]  -= DOT4(xr0, lc3);
                    a16[4]  -= DOT4(xr1, lc0); a16[5]  -= DOT4(xr1, lc1);
                    a16[6]  -= DOT4(xr1, lc2); a16[7]  -= DOT4(xr1, lc3);
                    a16[8]  -= DOT4(xr2, lc0); a16[9]  -= DOT4(xr2, lc1);
                    a16[10] -= DOT4(xr2, lc2); a16[11] -= DOT4(xr2, lc3);
                    a16[12] -= DOT4(xr3, lc0); a16[13] -= DOT4(xr3, lc1);
                    a16[14] -= DOT4(xr3, lc2); a16[15] -= DOT4(xr3, lc3);
#undef DOT4
                    if (ta == jb + 1 && tb == jb + 1)
                        diag_ldl(a16, cb + 4, LbD, Lc, invDall);
                } else if (t >= 137 && t < 137 + (15 - jb)) {
                    int g = jb + 1 + (t - 137);
                    int r0 = g << 2;
                    float y0 = yv[cb + 0], y1 = yv[cb + 1],
                          y2 = yv[cb + 2], y3 = yv[cb + 3];
                    const float4* L4 = (const float4*)Lb;
#pragma unroll
                    for (int r = 0; r < 4; r++) {
                        float4 lr = L4[r0 + r];
                        yv[r0 + r] -= lr.x * y0 + lr.y * y1 + lr.z * y2 + lr.w * y3;
                    }
                }
                HBAR();
            }
        }

        // --- backward solve: warp 0 via shfl ---
        if (w == 0) {
            float w0 = yv[lane] * invDall[lane];
            float w1 = yv[lane + 32] * invDall[lane + 32];
            for (int j = CDIM - 1; j >= 0; j--) {
                float src = (j >= 32) ? w1 : w0;
                float xj = __shfl_sync(0xffffffffu, src, j & 31);
                xj = scrub(xj);
                if (lane == (j & 31)) dzv[j] = xj;
                if (lane < j)      w0 -= Lc[lane * LCS + j] * xj;
                if (lane + 32 < j) w1 -= Lc[(lane + 32) * LCS + j] * xj;
            }
        }
        HBAR();

        // --- I: ds, dlam, alpha candidates -> red[16..23] ---
        float ac = CLAMP_BIG;
        if (t < MDIM) {
            float acc = -rp_ - dot64_f2(dzv, Gp + t * GS);
            ds_ = scrub(acc);
            dl_ = scrub((mu - sl_ - l_ * ds_) / s_);
            float x1 = (ds_ < 0.f) ? (-s_ / ds_) : CLAMP_BIG;
            float x2 = (dl_ < 0.f) ? (-l_ / dl_) : CLAMP_BIG;
            ac = fminf(x1, x2);
        }
        ac = warp_rmin(ac);
        if (lane == 0) red[16 + w] = ac;
        HBAR();
    }

    // final step for z (20th update), in registers
    float alphaF = 0.99f * fminf(1.f, min8(red + 16));
    float zf = (t < CDIM) ? (zv[t] + alphaF * dzv[t]) : -CLAMP_BIG;

    // --- log_softmax over 64 classes ---
    float mz = warp_rmax(zf);
    if (lane == 0) red[w] = mz;
    HBAR();
    float zmax = fmaxf(fmaxf(fmaxf(red[0], red[1]), fmaxf(red[2], red[3])),
                       fmaxf(fmaxf(red[4], red[5]), fmaxf(red[6], red[7])));
    float ev = (t < CDIM) ? expf(zf - zmax) : 0.f;
    ev = warp_rsum(ev);
    if (lane == 0) red[8 + w] = ev;
    HBAR();
    float ssum = red[8] + red[9] + red[10] + red[11] +
                 red[12] + red[13] + red[14] + red[15];
    float lse = logf(ssum);
    if (t < CDIM)
        out[(size_t)b * CDIM + t] = zf - zmax - lse;
#undef HBAR
}

extern "C" void kernel_launch(void* const* d_in, const int* in_sizes, int n_in,
                              void* d_out, int out_size)
{
    const float* x    = (const float*)d_in[0];
    const float* W1   = (const float*)d_in[1];
    const float* b1   = (const float*)d_in[2];
    const float* W2   = (const float*)d_in[3];
    const float* b2   = (const float*)d_in[4];
    const float* bn1g = (const float*)d_in[5];
    const float* bn1b = (const float*)d_in[6];
    const float* bn2g = (const float*)d_in[7];
    const float* bn2b = (const float*)d_in[8];
    const float* L    = (const float*)d_in[9];
    const float* G    = (const float*)d_in[10];
    const float* z0   = (const float*)d_in[11];
    const float* s0   = (const float*)d_in[12];
    float* out = (float*)d_out;

    cudaFuncSetAttribute(ipm_kernel, cudaFuncAttributeMaxDynamicSharedMemorySize,
                         SM_FLOATS * sizeof(float));

    prep_kernel<<<1, 256>>>(L, G, z0, s0);
    gemm1_kernel<<<dim3(HDIM / 64, BATCH / 64), 256>>>(x, W1, b1);
    bn1_stats_kernel<<<HDIM / 64, 256>>>(bn1g, bn1b);
    gemm2_kernel<<<BATCH / 64, 256>>>(W2, b2);
    bn2_stats_kernel<<<CDIM, 256>>>(bn2g, bn2b);
    ipm_kernel<<<BATCH / 2, 512, SM_FLOATS * sizeof(float)>>>(G, out);
}

// round 11
// speedup vs baseline: 1.1108x; 1.1094x over previous
#include <cuda_runtime.h>
#include <math.h>

#define BATCH 2048
#define FDIM  1024
#define HDIM  1024
#define CDIM  64
#define MDIM  200
#define NITER 20
#define SIGMA 0.1f
#define EPSQP 1e-4f
#define BNEPS 1e-5f
#define CLAMP_BIG 1e30f

__device__ float g_y1[BATCH * HDIM];
__device__ float g_pp[BATCH * CDIM];
__device__ float g_a1[HDIM];
__device__ float g_c1[HDIM];
__device__ float g_a2[CDIM];
__device__ float g_c2[CDIM];
__device__ float g_Q[CDIM * CDIM];
__device__ float g_h[MDIM];

typedef unsigned long long ull;
__device__ __forceinline__ ull f2dup(float s) {
    ull r; asm("mov.b64 %0, {%1, %1};" : "=l"(r) : "f"(s)); return r;
}
__device__ __forceinline__ ull f2pack(float lo, float hi) {
    ull r; asm("mov.b64 %0, {%1, %2};" : "=l"(r) : "f"(lo), "f"(hi)); return r;
}
__device__ __forceinline__ ull f2mul(ull a, ull b) {
    ull d; asm("mul.rn.f32x2 %0, %1, %2;" : "=l"(d) : "l"(a), "l"(b)); return d;
}
__device__ __forceinline__ ull f2fma(ull a, ull b, ull c) {
    ull d; asm("fma.rn.f32x2 %0, %1, %2, %3;" : "=l"(d) : "l"(a), "l"(b), "l"(c)); return d;
}
__device__ __forceinline__ void f2unpack(ull v, float& lo, float& hi) {
    asm("mov.b64 {%0, %1}, %2;" : "=f"(lo), "=f"(hi) : "l"(v));
}

__global__ void prep_kernel(const float* __restrict__ L, const float* __restrict__ G,
                            const float* __restrict__ z0, const float* __restrict__ s0)
{
    int t = threadIdx.x;
    for (int idx = t; idx < CDIM * CDIM; idx += 256) {
        int i = idx >> 6, j = idx & 63;
        int km = i < j ? i : j;
        float acc = (i == j) ? EPSQP : 0.f;
        for (int k = 0; k <= km; k++) acc += L[i * CDIM + k] * L[j * CDIM + k];
        g_Q[idx] = acc;
    }
    for (int m = t; m < MDIM; m += 256) {
        float acc = s0[m];
        for (int i = 0; i < CDIM; i++) acc += G[m * CDIM + i] * z0[i];
        g_h[m] = acc;
    }
}

__global__ void __launch_bounds__(256) gemm1_kernel(const float* __restrict__ x,
                                                    const float* __restrict__ W1,
                                                    const float* __restrict__ b1)
{
    __shared__ float As[16][64];
    __shared__ float Bs[16][64];
    int tid = threadIdx.x;
    int hb = blockIdx.x * 64, rb = blockIdx.y * 64;
    int lr = tid >> 2, lk = (tid & 3) << 2;
    int ty = tid >> 4, tx = tid & 15;
    float acc[4][4];
#pragma unroll
    for (int u = 0; u < 4; u++)
#pragma unroll
        for (int v = 0; v < 4; v++) acc[u][v] = 0.f;

    const float* xp = x + (size_t)(rb + lr) * FDIM + lk;
    const float* wp = W1 + (size_t)(hb + lr) * FDIM + lk;

    for (int k0 = 0; k0 < FDIM; k0 += 16) {
        float4 av = *(const float4*)(xp + k0);
        float4 bv = *(const float4*)(wp + k0);
        As[lk + 0][lr] = av.x; As[lk + 1][lr] = av.y; As[lk + 2][lr] = av.z; As[lk + 3][lr] = av.w;
        Bs[lk + 0][lr] = bv.x; Bs[lk + 1][lr] = bv.y; Bs[lk + 2][lr] = bv.z; Bs[lk + 3][lr] = bv.w;
        __syncthreads();
#pragma unroll
        for (int k = 0; k < 16; k++) {
            float4 a4 = *(const float4*)&As[k][ty << 2];
            float4 b4 = *(const float4*)&Bs[k][tx << 2];
            float a_[4] = {a4.x, a4.y, a4.z, a4.w};
            float b_[4] = {b4.x, b4.y, b4.z, b4.w};
#pragma unroll
            for (int u = 0; u < 4; u++)
#pragma unroll
                for (int v = 0; v < 4; v++) acc[u][v] += a_[u] * b_[v];
        }
        __syncthreads();
    }
#pragma unroll
    for (int u = 0; u < 4; u++) {
        int r = rb + (ty << 2) + u;
        int h = hb + (tx << 2);
        float4 o;
        o.x = fmaxf(acc[u][0] + b1[h + 0], 0.f);
        o.y = fmaxf(acc[u][1] + b1[h + 1], 0.f);
        o.z = fmaxf(acc[u][2] + b1[h + 2], 0.f);
        o.w = fmaxf(acc[u][3] + b1[h + 3], 0.f);
        *(float4*)&g_y1[(size_t)r * HDIM + h] = o;
    }
}

__global__ void bn1_stats_kernel(const float* __restrict__ gamma, const float* __restrict__ beta)
{
    __shared__ float s1[256], s2[256];
    int tid = threadIdx.x;
    int colBase = blockIdx.x * 64;
    int col = colBase + (tid & 63);
    int rs = tid >> 6;
    float sum = 0.f, sq = 0.f;
    for (int r = rs; r < BATCH; r += 4) {
        float v = g_y1[(size_t)r * HDIM + col];
        sum += v; sq += v * v;
    }
    s1[tid] = sum; s2[tid] = sq;
    __syncthreads();
    if (tid < 64) {
        float S = s1[tid] + s1[tid + 64] + s1[tid + 128] + s1[tid + 192];
        float P = s2[tid] + s2[tid + 64] + s2[tid + 128] + s2[tid + 192];
        float mean = S * (1.f / BATCH);
        float var = P * (1.f / BATCH) - mean * mean;
        float a = gamma[colBase + tid] / sqrtf(var + BNEPS);
        g_a1[colBase + tid] = a;
        g_c1[colBase + tid] = beta[colBase + tid] - mean * a;
    }
}

__global__ void __launch_bounds__(256) gemm2_kernel(const float* __restrict__ W2,
                                                    const float* __restrict__ b2)
{
    __shared__ float As[16][64];
    __shared__ float Bs[16][64];
    __shared__ float a1s[HDIM];
    __shared__ float c1s[HDIM];
    int tid = threadIdx.x;
    for (int i = tid; i < HDIM; i += 256) { a1s[i] = g_a1[i]; c1s[i] = g_c1[i]; }
    __syncthreads();

    int rb = blockIdx.x * 64;
    int lr = tid >> 2, lk = (tid & 3) << 2;
    int ty = tid >> 4, tx = tid & 15;
    float acc[4][4];
#pragma unroll
    for (int u = 0; u < 4; u++)
#pragma unroll
        for (int v = 0; v < 4; v++) acc[u][v] = 0.f;

    const float* yp = g_y1 + (size_t)(rb + lr) * HDIM + lk;
    const float* wp = W2 + (size_t)lr * HDIM + lk;

    for (int k0 = 0; k0 < HDIM; k0 += 16) {
        float4 av = *(const float4*)(yp + k0);
        float4 bv = *(const float4*)(wp + k0);
        As[lk + 0][lr] = av.x * a1s[k0 + lk + 0] + c1s[k0 + lk + 0];
        As[lk + 1][lr] = av.y * a1s[k0 + lk + 1] + c1s[k0 + lk + 1];
        As[lk + 2][lr] = av.z * a1s[k0 + lk + 2] + c1s[k0 + lk + 2];
        As[lk + 3][lr] = av.w * a1s[k0 + lk + 3] + c1s[k0 + lk + 3];
        Bs[lk + 0][lr] = bv.x; Bs[lk + 1][lr] = bv.y; Bs[lk + 2][lr] = bv.z; Bs[lk + 3][lr] = bv.w;
        __syncthreads();
#pragma unroll
        for (int k = 0; k < 16; k++) {
            float4 a4 = *(const float4*)&As[k][ty << 2];
            float4 b4 = *(const float4*)&Bs[k][tx << 2];
            float a_[4] = {a4.x, a4.y, a4.z, a4.w};
            float b_[4] = {b4.x, b4.y, b4.z, b4.w};
#pragma unroll
            for (int u = 0; u < 4; u++)
#pragma unroll
                for (int v = 0; v < 4; v++) acc[u][v] += a_[u] * b_[v];
        }
        __syncthreads();
    }
#pragma unroll
    for (int u = 0; u < 4; u++) {
        int r = rb + (ty << 2) + u;
        int n = tx << 2;
        float4 o;
        o.x = fmaxf(acc[u][0] + b2[n + 0], 0.f);
        o.y = fmaxf(acc[u][1] + b2[n + 1], 0.f);
        o.z = fmaxf(acc[u][2] + b2[n + 2], 0.f);
        o.w = fmaxf(acc[u][3] + b2[n + 3], 0.f);
        *(float4*)&g_pp[(size_t)r * CDIM + n] = o;
    }
}

__global__ void bn2_stats_kernel(const float* __restrict__ gamma, const float* __restrict__ beta)
{
    __shared__ float s1[256], s2[256];
    int tid = threadIdx.x;
    int col = blockIdx.x;
    float sum = 0.f, sq = 0.f;
    for (int r = tid; r < BATCH; r += 256) {
        float v = g_pp[(size_t)r * CDIM + col];
        sum += v; sq += v * v;
    }
    s1[tid] = sum; s2[tid] = sq;
    __syncthreads();
    for (int s = 128; s > 0; s >>= 1) {
        if (tid < s) { s1[tid] += s1[tid + s]; s2[tid] += s2[tid + s]; }
        __syncthreads();
    }
    if (tid == 0) {
        float mean = s1[0] * (1.f / BATCH);
        float var = s2[0] * (1.f / BATCH) - mean * mean;
        float a = gamma[col] / sqrtf(var + BNEPS);
        g_a2[col] = a;
        g_c2[col] = beta[col] - mean * a;
    }
}

// ---------------- IPM ----------------
#define GS 66
#define LCS 66
#define SH_FLOATS   (MDIM * GS + 200)
#define HALF_FLOATS (4224 + 256 + 256 + 16 + 5*64 + 2*200 + 40)
#define SM_FLOATS   (SH_FLOATS + 2 * HALF_FLOATS)

__device__ __forceinline__ float scrub(float v)
{
    return fminf(fmaxf(v, -CLAMP_BIG), CLAMP_BIG);
}
__device__ __forceinline__ float warp_rsum(float v)
{
#pragma unroll
    for (int s = 16; s > 0; s >>= 1) v += __shfl_xor_sync(0xffffffffu, v, s);
    return v;
}
__device__ __forceinline__ float warp_rmin(float v)
{
#pragma unroll
    for (int s = 16; s > 0; s >>= 1) v = fminf(v, __shfl_xor_sync(0xffffffffu, v, s));
    return v;
}
__device__ __forceinline__ float warp_rmax(float v)
{
#pragma unroll
    for (int s = 16; s > 0; s >>= 1) v = fmaxf(v, __shfl_xor_sync(0xffffffffu, v, s));
    return v;
}
__device__ __forceinline__ float dot64_f2(const float* a, const float* b)
{
    ull acc2 = 0ull;
#pragma unroll 8
    for (int i = 0; i < CDIM; i += 2) {
        float2 x = *(const float2*)(a + i);
        float2 y = *(const float2*)(b + i);
        acc2 = f2fma(f2pack(x.x, x.y), f2pack(y.x, y.y), acc2);
    }
    float lo, hi; f2unpack(acc2, lo, hi);
    return lo + hi;
}
__device__ __forceinline__ float min8(const float* red)
{
    return fminf(fminf(fminf(red[0], red[1]), fminf(red[2], red[3])),
                 fminf(fminf(red[4], red[5]), fminf(red[6], red[7])));
}

__device__ __forceinline__ void diag_ldl(float* a16, int cb, float* LbD,
                                         float* Lc, float* invDall)
{
#pragma unroll
    for (int c = 0; c < 4; c++) {
        float h0 = a16[c * 4 + c];
        float v = h0;
#pragma unroll
        for (int k = 0; k < 4; k++)
            if (k < c) v -= a16[c * 4 + k] * LbD[c * 4 + k];
        float piv = fmaxf(v, 1e-12f * fmaxf(h0, EPSQP));
        float inv = 1.f / piv;
        invDall[cb + c] = inv;
#pragma unroll
        for (int r = 0; r < 4; r++) {
            if (r > c) {
                float x = a16[r * 4 + c];
#pragma unroll
                for (int k = 0; k < 4; k++)
                    if (k < c) x -= a16[r * 4 + k] * LbD[c * 4 + k];
                a16[r * 4 + c] = x;
                float l = x * inv;
                LbD[r * 4 + c] = l;
                Lc[(cb + c) * LCS + (cb + r)] = l;
            }
        }
    }
}

__global__ void __launch_bounds__(512, 2) ipm_kernel(const float* __restrict__ G,
                                                     float* __restrict__ out)
{
    extern __shared__ float sm[];
    float* Gp = sm;
    float* hh = Gp + MDIM * GS;
    int tid  = threadIdx.x;
    int half = tid >> 8;
    int t    = tid & 255;
    int barid = 1 + half;

    float* ms      = hh + 200 + half * HALF_FLOATS;
    float* Lc      = ms;            // [64*66]
    float* Xb      = Lc + 4224;     // [64*4]
    float* Lb      = Xb + 256;      // [64*4]
    float* LbD     = Lb + 256;      // [16]
    float* invDall = LbD + 16;      // [64]
    float* yv      = invDall + 64;  // [64]
    float* dzv     = yv + 64;       // [64]
    float* pb      = dzv + 64;      // [64]
    float* zv      = pb + 64;       // [64]
    float* dv      = zv + 64;       // [200]
    float* lwv     = dv + 200;      // [200]
    float* red     = lwv + 200;     // [40]

#define HBAR() asm volatile("bar.sync %0, %1;" :: "r"(barid), "r"(256) : "memory")

    int b = blockIdx.x * 2 + half;
    int w = t >> 5;
    int lane = t & 31;

    for (int idx = tid; idx < MDIM * CDIM; idx += 512) {
        int m = idx >> 6, i = idx & 63;
        Gp[m * GS + i] = G[idx];
    }
    if (tid < MDIM) hh[tid] = g_h[tid];
    __syncthreads();

    float s_ = 1.f, l_ = 1.f, sl_ = 1.f;
    float rp_ = (t < MDIM) ? (1.f - hh[t]) : 0.f;
    float ds_ = 0.f, dl_ = 0.f;

    if (t < CDIM) {
        pb[t] = g_a2[t] * g_pp[(size_t)b * CDIM + t] + g_c2[t];
        zv[t] = 0.f;
    }

    // ---- broadcast-friendly warp-rect tile mapping (warps 0-4 per half) ----
    // exact cover of all 136 lower-tri tiles + 24 benign upper tiles
    bool tact = false;
    int ta = 0, tb = 0;
    if (t < 160) {
        int wi = t >> 5, ln = t & 31;
        tact = true;
        if (wi == 0)      { ta = (ln >> 2);       tb = (ln & 3); }
        else if (wi == 1) { ta = 8 + (ln >> 2);   tb = (ln & 3); }
        else if (wi == 2) { ta = 4 + (ln >> 2);   tb = 4 + (ln & 3); }
        else if (wi == 3) {
            if (ln < 16)  { ta = 12 + (ln >> 2);  tb = 4 + (ln & 3); }
            else { int lm = ln - 16; ta = 12 + (lm >> 2); tb = 12 + (lm & 3); }
        } else            { ta = 8 + (ln >> 2);   tb = 8 + (ln & 3); }
    }
    int ti = ta << 2, tj = tb << 2;

    HBAR();

    float mu = 0.f;
    for (int iter = 0; iter < NITER; iter++) {
        // --- top: apply previous step + mu partials ---
        if (iter > 0) {
            float alpha = 0.99f * fminf(1.f, min8(red + 16));
            if (t < MDIM) {
                s_ = fmaxf(s_ + alpha * ds_, 1e-30f);
                l_ = fmaxf(l_ + alpha * dl_, 1e-30f);
                rp_ *= (1.f - alpha);
            }
            if (t < CDIM) zv[t] += alpha * dzv[t];
        }
        float cand = 0.f;
        if (t < MDIM) {
            sl_ = s_ * l_;
            dv[t] = l_ / s_;
            cand = sl_;
        }
        cand = warp_rsum(cand);
        if (lane == 0) red[w] = cand;
        HBAR();

        // --- B: mu, lam+w ---
        mu = SIGMA * (1.f / MDIM) *
             (red[0] + red[1] + red[2] + red[3] + red[4] + red[5] + red[6] + red[7]);
        if (t < MDIM) {
            float wv = (mu - sl_ + l_ * rp_) / s_;
            lwv[t] = l_ + wv;
        }
        HBAR();

        // --- CF: H tiles in registers (warps 0-4) || rhs (160<=t<224) ---
        float a16[16];
        if (tact) {
            ull accA[4], accB[4];
            {
                float4 q0 = *(const float4*)&g_Q[(ti + 0) * CDIM + tj];
                float4 q1 = *(const float4*)&g_Q[(ti + 1) * CDIM + tj];
                float4 q2 = *(const float4*)&g_Q[(ti + 2) * CDIM + tj];
                float4 q3 = *(const float4*)&g_Q[(ti + 3) * CDIM + tj];
                accA[0] = f2pack(q0.x, q1.x); accA[1] = f2pack(q0.y, q1.y);
                accA[2] = f2pack(q0.z, q1.z); accA[3] = f2pack(q0.w, q1.w);
                accB[0] = f2pack(q2.x, q3.x); accB[1] = f2pack(q2.y, q3.y);
                accB[2] = f2pack(q2.z, q3.z); accB[3] = f2pack(q2.w, q3.w);
            }
#pragma unroll 2
            for (int m = 0; m < MDIM; m++) {
                const float* gr = Gp + m * GS;
                ull dm2 = f2dup(dv[m]);
                float2 fa01 = *(const float2*)(gr + ti);
                float2 fa23 = *(const float2*)(gr + ti + 2);
                float2 fb01 = *(const float2*)(gr + tj);
                float2 fb23 = *(const float2*)(gr + tj + 2);
                ull sa01 = f2mul(f2pack(fa01.x, fa01.y), dm2);
                ull sa23 = f2mul(f2pack(fa23.x, fa23.y), dm2);
                ull db0 = f2dup(fb01.x), db1 = f2dup(fb01.y);
                ull db2 = f2dup(fb23.x), db3 = f2dup(fb23.y);
                accA[0] = f2fma(sa01, db0, accA[0]);
                accA[1] = f2fma(sa01, db1, accA[1]);
                accA[2] = f2fma(sa01, db2, accA[2]);
                accA[3] = f2fma(sa01, db3, accA[3]);
                accB[0] = f2fma(sa23, db0, accB[0]);
                accB[1] = f2fma(sa23, db1, accB[1]);
                accB[2] = f2fma(sa23, db2, accB[2]);
                accB[3] = f2fma(sa23, db3, accB[3]);
            }
#pragma unroll
            for (int c = 0; c < 4; c++) {
                f2unpack(accA[c], a16[0 * 4 + c], a16[1 * 4 + c]);
                f2unpack(accB[c], a16[2 * 4 + c], a16[3 * 4 + c]);
            }
            if (t == 0) diag_ldl(a16, 0, LbD, Lc, invDall);
        } else if (t >= 160 && t < 160 + CDIM) {
            int c = t - 160;
            float acc = pb[c] + dot64_f2(zv, &g_Q[c * CDIM]);
#pragma unroll 4
            for (int m = 0; m < MDIM; m++) acc += lwv[m] * Gp[m * GS + c];
            yv[c] = -acc;
        }
        HBAR();

        // --- blocked LDL^T (4-wide) + fused forward solve on warp 7 ---
        for (int jb = 0; jb < 16; jb++) {
            int cb = jb << 2;
            if (tact && tb == jb && ta > jb) {
#pragma unroll
                for (int c = 0; c < 4; c++) {
                    float inv = invDall[cb + c];
                    float l0 = LbD[c * 4 + 0];
                    float l1 = LbD[c * 4 + 1];
                    float l2 = LbD[c * 4 + 2];
#pragma unroll
                    for (int r = 0; r < 4; r++) {
                        float x = a16[r * 4 + c];
                        if (c > 0) x -= a16[r * 4 + 0] * l0;
                        if (c > 1) x -= a16[r * 4 + 1] * l1;
                        if (c > 2) x -= a16[r * 4 + 2] * l2;
                        a16[r * 4 + c] = x;
                        float l = x * inv;
                        Xb[(ti + r) * 4 + c] = x;
                        Lb[(ti + r) * 4 + c] = l;
                        Lc[(cb + c) * LCS + (ti + r)] = l;
                    }
                }
            } else if (t == 224) {
#pragma unroll
                for (int c = 0; c < 4; c++) {
                    float yc = yv[cb + c];
#pragma unroll
                    for (int k = 0; k < 4; k++)
                        if (k < c) yc -= LbD[c * 4 + k] * yv[cb + k];
                    yv[cb + c] = yc;
                }
            }
            HBAR();
            if (jb < 15) {
                if (tact && ta > jb && tb > jb) {
                    const float4* X4 = (const float4*)Xb;
                    const float4* L4 = (const float4*)Lb;
                    float4 xr0 = X4[ti + 0], xr1 = X4[ti + 1],
                           xr2 = X4[ti + 2], xr3 = X4[ti + 3];
                    float4 lc0 = L4[tj + 0], lc1 = L4[tj + 1],
                           lc2 = L4[tj + 2], lc3 = L4[tj + 3];
#define DOT4(p, q) (p.x * q.x + p.y * q.y + p.z * q.z + p.w * q.w)
                    a16[0]  -= DOT4(xr0, lc0); a16[1]  -= DOT4(xr0, lc1);
                    a16[2]  -= DOT4(xr0, lc2); a16[3]  -= DOT4(xr0, lc3);
                    a16[4]  -= DOT4(xr1, lc0); a16[5]  -= DOT4(xr1, lc1);
                    a16[6]  -= DOT4(xr1, lc2); a16[7]  -= DOT4(xr1, lc3);
                    a16[8]  -= DOT4(xr2, lc0); a16[9]  -= DOT4(xr2, lc1);
                    a16[10] -= DOT4(xr2, lc2); a16[11] -= DOT4(xr2, lc3);
                    a16[12] -= DOT4(xr3, lc0); a16[13] -= DOT4(xr3, lc1);
                    a16[14] -= DOT4(xr3, lc2); a16[15] -= DOT4(xr3, lc3);
#undef DOT4
                    if (ta == jb + 1 && tb == jb + 1)
                        diag_ldl(a16, cb + 4, LbD, Lc, invDall);
                } else if (t >= 225 && t < 225 + (15 - jb)) {
                    int g = jb + 1 + (t - 225);
                    int r0 = g << 2;
                    float y0 = yv[cb + 0], y1 = yv[cb + 1],
                          y2 = yv[cb + 2], y3 = yv[cb + 3];
                    const float4* L4 = (const float4*)Lb;
#pragma unroll
                    for (int r = 0; r < 4; r++) {
                        float4 lr = L4[r0 + r];
                        yv[r0 + r] -= lr.x * y0 + lr.y * y1 + lr.z * y2 + lr.w * y3;
                    }
                }
                HBAR();
            }
        }

        // --- backward solve: warp 0 via shfl ---
        if (w == 0) {
            float w0 = yv[lane] * invDall[lane];
            float w1 = yv[lane + 32] * invDall[lane + 32];
            for (int j = CDIM - 1; j >= 0; j--) {
                float src = (j >= 32) ? w1 : w0;
                float xj = __shfl_sync(0xffffffffu, src, j & 31);
                xj = scrub(xj);
                if (lane == (j & 31)) dzv[j] = xj;
                if (lane < j)      w0 -= Lc[lane * LCS + j] * xj;
                if (lane + 32 < j) w1 -= Lc[(lane + 32) * LCS + j] * xj;
            }
        }
        HBAR();

        // --- I: ds, dlam, alpha candidates -> red[16..23] ---
        float ac = CLAMP_BIG;
        if (t < MDIM) {
            float acc = -rp_ - dot64_f2(dzv, Gp + t * GS);
            ds_ = scrub(acc);
            dl_ = scrub((mu - sl_ - l_ * ds_) / s_);
            float x1 = (ds_ < 0.f) ? (-s_ / ds_) : CLAMP_BIG;
            float x2 = (dl_ < 0.f) ? (-l_ / dl_) : CLAMP_BIG;
            ac = fminf(x1, x2);
        }
        ac = warp_rmin(ac);
        if (lane == 0) red[16 + w] = ac;
        HBAR();
    }

    float alphaF = 0.99f * fminf(1.f, min8(red + 16));
    float zf = (t < CDIM) ? (zv[t] + alphaF * dzv[t]) : -CLAMP_BIG;

    float mz = warp_rmax(zf);
    if (lane == 0) red[w] = mz;
    HBAR();
    float zmax = fmaxf(fmaxf(fmaxf(red[0], red[1]), fmaxf(red[2], red[3])),
                       fmaxf(fmaxf(red[4], red[5]), fmaxf(red[6], red[7])));
    float ev = (t < CDIM) ? expf(zf - zmax) : 0.f;
    ev = warp_rsum(ev);
    if (lane == 0) red[8 + w] = ev;
    HBAR();
    float ssum = red[8] + red[9] + red[10] + red[11] +
                 red[12] + red[13] + red[14] + red[15];
    float lse = logf(ssum);
    if (t < CDIM)
        out[(size_t)b * CDIM + t] = zf - zmax - lse;
#undef HBAR
}

extern "C" void kernel_launch(void* const* d_in, const int* in_sizes, int n_in,
                              void* d_out, int out_size)
{
    const float* x    = (const float*)d_in[0];
    const float* W1   = (const float*)d_in[1];
    const float* b1   = (const float*)d_in[2];
    const float* W2   = (const float*)d_in[3];
    const float* b2   = (const float*)d_in[4];
    const float* bn1g = (const float*)d_in[5];
    const float* bn1b = (const float*)d_in[6];
    const float* bn2g = (const float*)d_in[7];
    const float* bn2b = (const float*)d_in[8];
    const float* L    = (const float*)d_in[9];
    const float* G    = (const float*)d_in[10];
    const float* z0   = (const float*)d_in[11];
    const float* s0   = (const float*)d_in[12];
    float* out = (float*)d_out;

    cudaFuncSetAttribute(ipm_kernel, cudaFuncAttributeMaxDynamicSharedMemorySize,
                         SM_FLOATS * sizeof(float));

    prep_kernel<<<1, 256>>>(L, G, z0, s0);
    gemm1_kernel<<<dim3(HDIM / 64, BATCH / 64), 256>>>(x, W1, b1);
    bn1_stats_kernel<<<HDIM / 64, 256>>>(bn1g, bn1b);
    gemm2_kernel<<<BATCH / 64, 256>>>(W2, b2);
    bn2_stats_kernel<<<CDIM, 256>>>(bn2g, bn2b);
    ipm_kernel<<<BATCH / 2, 512, SM_FLOATS * sizeof(float)>>>(G, out);
}

// round 12
// speedup vs baseline: 1.1140x; 1.0029x over previous
#include <cuda_runtime.h>
#include <math.h>

#define BATCH 2048
#define FDIM  1024
#define HDIM  1024
#define CDIM  64
#define MDIM  200
#define NITER 20
#define SIGMA 0.1f
#define EPSQP 1e-4f
#define BNEPS 1e-5f
#define CLAMP_BIG 1e30f

__device__ float g_y1[BATCH * HDIM];
__device__ float g_pp[BATCH * CDIM];
__device__ float g_a1[HDIM];
__device__ float g_c1[HDIM];
__device__ float g_Q[CDIM * CDIM];
__device__ float g_h[MDIM];
__device__ float g_part1[32 * CDIM];   // per-block bn2 column sums
__device__ float g_part2[32 * CDIM];   // per-block bn2 column sq-sums

typedef unsigned long long ull;
__device__ __forceinline__ ull f2dup(float s) {
    ull r; asm("mov.b64 %0, {%1, %1};" : "=l"(r) : "f"(s)); return r;
}
__device__ __forceinline__ ull f2pack(float lo, float hi) {
    ull r; asm("mov.b64 %0, {%1, %2};" : "=l"(r) : "f"(lo), "f"(hi)); return r;
}
__device__ __forceinline__ ull f2mul(ull a, ull b) {
    ull d; asm("mul.rn.f32x2 %0, %1, %2;" : "=l"(d) : "l"(a), "l"(b)); return d;
}
__device__ __forceinline__ ull f2fma(ull a, ull b, ull c) {
    ull d; asm("fma.rn.f32x2 %0, %1, %2, %3;" : "=l"(d) : "l"(a), "l"(b), "l"(c)); return d;
}
__device__ __forceinline__ void f2unpack(ull v, float& lo, float& hi) {
    asm("mov.b64 {%0, %1}, %2;" : "=f"(lo), "=f"(hi) : "l"(v));
}

// ---------------- GEMM1: y1 = relu(x @ W1^T + b1) ----------------
__global__ void __launch_bounds__(256) gemm1_kernel(const float* __restrict__ x,
                                                    const float* __restrict__ W1,
                                                    const float* __restrict__ b1)
{
    __shared__ float As[16][64];
    __shared__ float Bs[16][64];
    int tid = threadIdx.x;
    int hb = blockIdx.x * 64, rb = blockIdx.y * 64;
    int lr = tid >> 2, lk = (tid & 3) << 2;
    int ty = tid >> 4, tx = tid & 15;
    float acc[4][4];
#pragma unroll
    for (int u = 0; u < 4; u++)
#pragma unroll
        for (int v = 0; v < 4; v++) acc[u][v] = 0.f;

    const float* xp = x + (size_t)(rb + lr) * FDIM + lk;
    const float* wp = W1 + (size_t)(hb + lr) * FDIM + lk;

    for (int k0 = 0; k0 < FDIM; k0 += 16) {
        float4 av = *(const float4*)(xp + k0);
        float4 bv = *(const float4*)(wp + k0);
        As[lk + 0][lr] = av.x; As[lk + 1][lr] = av.y; As[lk + 2][lr] = av.z; As[lk + 3][lr] = av.w;
        Bs[lk + 0][lr] = bv.x; Bs[lk + 1][lr] = bv.y; Bs[lk + 2][lr] = bv.z; Bs[lk + 3][lr] = bv.w;
        __syncthreads();
#pragma unroll
        for (int k = 0; k < 16; k++) {
            float4 a4 = *(const float4*)&As[k][ty << 2];
            float4 b4 = *(const float4*)&Bs[k][tx << 2];
            float a_[4] = {a4.x, a4.y, a4.z, a4.w};
            float b_[4] = {b4.x, b4.y, b4.z, b4.w};
#pragma unroll
            for (int u = 0; u < 4; u++)
#pragma unroll
                for (int v = 0; v < 4; v++) acc[u][v] += a_[u] * b_[v];
        }
        __syncthreads();
    }
#pragma unroll
    for (int u = 0; u < 4; u++) {
        int r = rb + (ty << 2) + u;
        int h = hb + (tx << 2);
        float4 o;
        o.x = fmaxf(acc[u][0] + b1[h + 0], 0.f);
        o.y = fmaxf(acc[u][1] + b1[h + 1], 0.f);
        o.z = fmaxf(acc[u][2] + b1[h + 2], 0.f);
        o.w = fmaxf(acc[u][3] + b1[h + 3], 0.f);
        *(float4*)&g_y1[(size_t)r * HDIM + h] = o;
    }
}

// ---------------- BN1 stats (blocks 0-15) + prep (block 16) ----------------
__global__ void bn1_prep_kernel(const float* __restrict__ gamma, const float* __restrict__ beta,
                                const float* __restrict__ L, const float* __restrict__ G,
                                const float* __restrict__ z0, const float* __restrict__ s0)
{
    int tid = threadIdx.x;
    if (blockIdx.x == 16) {
        // prep: Q = tril(L)tril(L)^T + eps I ; h = G z0 + s0
        for (int idx = tid; idx < CDIM * CDIM; idx += 256) {
            int i = idx >> 6, j = idx & 63;
            int km = i < j ? i : j;
            float acc = (i == j) ? EPSQP : 0.f;
            for (int k = 0; k <= km; k++) acc += L[i * CDIM + k] * L[j * CDIM + k];
            g_Q[idx] = acc;
        }
        for (int m = tid; m < MDIM; m += 256) {
            float acc = s0[m];
            for (int i = 0; i < CDIM; i++) acc += G[m * CDIM + i] * z0[i];
            g_h[m] = acc;
        }
        return;
    }
    __shared__ float s1[256], s2[256];
    int colBase = blockIdx.x * 64;
    int col = colBase + (tid & 63);
    int rs = tid >> 6;
    float sum = 0.f, sq = 0.f;
    for (int r = rs; r < BATCH; r += 4) {
        float v = g_y1[(size_t)r * HDIM + col];
        sum += v; sq += v * v;
    }
    s1[tid] = sum; s2[tid] = sq;
    __syncthreads();
    if (tid < 64) {
        float S = s1[tid] + s1[tid + 64] + s1[tid + 128] + s1[tid + 192];
        float P = s2[tid] + s2[tid + 64] + s2[tid + 128] + s2[tid + 192];
        float mean = S * (1.f / BATCH);
        float var = P * (1.f / BATCH) - mean * mean;
        float a = gamma[colBase + tid] / sqrtf(var + BNEPS);
        g_a1[colBase + tid] = a;
        g_c1[colBase + tid] = beta[colBase + tid] - mean * a;
    }
}

// ---------------- GEMM2 + bn2 per-block partial sums ----------------
__global__ void __launch_bounds__(256) gemm2_kernel(const float* __restrict__ W2,
                                                    const float* __restrict__ b2)
{
    __shared__ float As[16][64];
    __shared__ float Bs[16][64];
    __shared__ float a1s[HDIM];
    __shared__ float c1s[HDIM];
    int tid = threadIdx.x;
    for (int i = tid; i < HDIM; i += 256) { a1s[i] = g_a1[i]; c1s[i] = g_c1[i]; }
    __syncthreads();

    int rb = blockIdx.x * 64;
    int lr = tid >> 2, lk = (tid & 3) << 2;
    int ty = tid >> 4, tx = tid & 15;
    float acc[4][4];
#pragma unroll
    for (int u = 0; u < 4; u++)
#pragma unroll
        for (int v = 0; v < 4; v++) acc[u][v] = 0.f;

    const float* yp = g_y1 + (size_t)(rb + lr) * HDIM + lk;
    const float* wp = W2 + (size_t)lr * HDIM + lk;

    for (int k0 = 0; k0 < HDIM; k0 += 16) {
        float4 av = *(const float4*)(yp + k0);
        float4 bv = *(const float4*)(wp + k0);
        As[lk + 0][lr] = av.x * a1s[k0 + lk + 0] + c1s[k0 + lk + 0];
        As[lk + 1][lr] = av.y * a1s[k0 + lk + 1] + c1s[k0 + lk + 1];
        As[lk + 2][lr] = av.z * a1s[k0 + lk + 2] + c1s[k0 + lk + 2];
        As[lk + 3][lr] = av.w * a1s[k0 + lk + 3] + c1s[k0 + lk + 3];
        Bs[lk + 0][lr] = bv.x; Bs[lk + 1][lr] = bv.y; Bs[lk + 2][lr] = bv.z; Bs[lk + 3][lr] = bv.w;
        __syncthreads();
#pragma unroll
        for (int k = 0; k < 16; k++) {
            float4 a4 = *(const float4*)&As[k][ty << 2];
            float4 b4 = *(const float4*)&Bs[k][tx << 2];
            float a_[4] = {a4.x, a4.y, a4.z, a4.w};
            float b_[4] = {b4.x, b4.y, b4.z, b4.w};
#pragma unroll
            for (int u = 0; u < 4; u++)
#pragma unroll
                for (int v = 0; v < 4; v++) acc[u][v] += a_[u] * b_[v];
        }
        __syncthreads();
    }
    float cs[4] = {0.f, 0.f, 0.f, 0.f};
    float cq[4] = {0.f, 0.f, 0.f, 0.f};
#pragma unroll
    for (int u = 0; u < 4; u++) {
        int r = rb + (ty << 2) + u;
        int n = tx << 2;
        float4 o;
        o.x = fmaxf(acc[u][0] + b2[n + 0], 0.f);
        o.y = fmaxf(acc[u][1] + b2[n + 1], 0.f);
        o.z = fmaxf(acc[u][2] + b2[n + 2], 0.f);
        o.w = fmaxf(acc[u][3] + b2[n + 3], 0.f);
        cs[0] += o.x; cq[0] += o.x * o.x;
        cs[1] += o.y; cq[1] += o.y * o.y;
        cs[2] += o.z; cq[2] += o.z * o.z;
        cs[3] += o.w; cq[3] += o.w * o.w;
        *(float4*)&g_pp[(size_t)r * CDIM + n] = o;
    }
    // deterministic per-block column partials (reuse As/Bs)
    __syncthreads();
#pragma unroll
    for (int v = 0; v < 4; v++) { As[ty][(tx << 2) + v] = cs[v]; Bs[ty][(tx << 2) + v] = cq[v]; }
    __syncthreads();
    if (tid < 64) {
        float S = 0.f, P = 0.f;
#pragma unroll
        for (int g = 0; g < 16; g++) { S += As[g][tid]; P += Bs[g][tid]; }
        g_part1[blockIdx.x * CDIM + tid] = S;
        g_part2[blockIdx.x * CDIM + tid] = P;
    }
}

// ---------------- IPM ----------------
#define GS 66
#define LCS 66
#define SH_FLOATS   (MDIM * GS + 200)
#define HALF_FLOATS (4224 + 256 + 256 + 16 + 5*64 + 2*200 + 40)
#define SM_FLOATS   (SH_FLOATS + 2 * HALF_FLOATS)

__device__ __forceinline__ float scrub(float v)
{
    return fminf(fmaxf(v, -CLAMP_BIG), CLAMP_BIG);
}
__device__ __forceinline__ float warp_rsum(float v)
{
#pragma unroll
    for (int s = 16; s > 0; s >>= 1) v += __shfl_xor_sync(0xffffffffu, v, s);
    return v;
}
__device__ __forceinline__ float warp_rmin(float v)
{
#pragma unroll
    for (int s = 16; s > 0; s >>= 1) v = fminf(v, __shfl_xor_sync(0xffffffffu, v, s));
    return v;
}
__device__ __forceinline__ float warp_rmax(float v)
{
#pragma unroll
    for (int s = 16; s > 0; s >>= 1) v = fmaxf(v, __shfl_xor_sync(0xffffffffu, v, s));
    return v;
}
__device__ __forceinline__ float dot64_f2(const float* a, const float* b)
{
    ull acc2 = 0ull;
#pragma unroll 8
    for (int i = 0; i < CDIM; i += 2) {
        float2 x = *(const float2*)(a + i);
        float2 y = *(const float2*)(b + i);
        acc2 = f2fma(f2pack(x.x, x.y), f2pack(y.x, y.y), acc2);
    }
    float lo, hi; f2unpack(acc2, lo, hi);
    return lo + hi;
}
__device__ __forceinline__ float min8(const float* red)
{
    return fminf(fminf(fminf(red[0], red[1]), fminf(red[2], red[3])),
                 fminf(fminf(red[4], red[5]), fminf(red[6], red[7])));
}

__device__ __forceinline__ void diag_ldl(float* a16, int cb, float* LbD,
                                         float* Lc, float* invDall)
{
#pragma unroll
    for (int c = 0; c < 4; c++) {
        float h0 = a16[c * 4 + c];
        float v = h0;
#pragma unroll
        for (int k = 0; k < 4; k++)
            if (k < c) v -= a16[c * 4 + k] * LbD[c * 4 + k];
        float piv = fmaxf(v, 1e-12f * fmaxf(h0, EPSQP));
        float inv = 1.f / piv;
        invDall[cb + c] = inv;
#pragma unroll
        for (int r = 0; r < 4; r++) {
            if (r > c) {
                float x = a16[r * 4 + c];
#pragma unroll
                for (int k = 0; k < 4; k++)
                    if (k < c) x -= a16[r * 4 + k] * LbD[c * 4 + k];
                a16[r * 4 + c] = x;
                float l = x * inv;
                LbD[r * 4 + c] = l;
                Lc[(cb + c) * LCS + (cb + r)] = l;
            }
        }
    }
}

__global__ void __launch_bounds__(512, 2) ipm_kernel(const float* __restrict__ G,
                                                     const float* __restrict__ bn2g,
                                                     const float* __restrict__ bn2b,
                                                     float* __restrict__ out)
{
    extern __shared__ float sm[];
    float* Gp = sm;
    float* hh = Gp + MDIM * GS;
    int tid  = threadIdx.x;
    int half = tid >> 8;
    int t    = tid & 255;
    int barid = 1 + half;

    float* ms      = hh + 200 + half * HALF_FLOATS;
    float* Lc      = ms;            // [64*66]
    float* Xb      = Lc + 4224;     // [64*4]
    float* Lb      = Xb + 256;      // [64*4]
    float* LbD     = Lb + 256;      // [16]
    float* invDall = LbD + 16;      // [64]
    float* yv      = invDall + 64;  // [64]
    float* dzv     = yv + 64;       // [64]
    float* pb      = dzv + 64;      // [64]
    float* zv      = pb + 64;       // [64]
    float* dv      = zv + 64;       // [200]
    float* lwv     = dv + 200;      // [200]
    float* red     = lwv + 200;     // [40]

#define HBAR() asm volatile("bar.sync %0, %1;" :: "r"(barid), "r"(256) : "memory")

    int b = blockIdx.x * 2 + half;
    int w = t >> 5;
    int lane = t & 31;

    for (int idx = tid; idx < MDIM * CDIM; idx += 512) {
        int m = idx >> 6, i = idx & 63;
        Gp[m * GS + i] = G[idx];
    }
    if (tid < MDIM) hh[tid] = g_h[tid];
    __syncthreads();

    float s_ = 1.f, l_ = 1.f, sl_ = 1.f;
    float rp_ = (t < MDIM) ? (1.f - hh[t]) : 0.f;
    float ds_ = 0.f, dl_ = 0.f;

    if (t < CDIM) {
        // fold bn2 from gemm2 partials (deterministic, L2-hot)
        float S = 0.f, P = 0.f;
#pragma unroll 4
        for (int blk = 0; blk < 32; blk++) {
            S += __ldg(&g_part1[blk * CDIM + t]);
            P += __ldg(&g_part2[blk * CDIM + t]);
        }
        float mean = S * (1.f / BATCH);
        float var = P * (1.f / BATCH) - mean * mean;
        float a2 = bn2g[t] / sqrtf(var + BNEPS);
        float c2 = bn2b[t] - mean * a2;
        pb[t] = a2 * g_pp[(size_t)b * CDIM + t] + c2;
        zv[t] = 0.f;
    }

    // broadcast-friendly warp-rect tile mapping (warps 0-4 per half)
    bool tact = false;
    int ta = 0, tb = 0;
    if (t < 160) {
        int wi = t >> 5, ln = t & 31;
        tact = true;
        if (wi == 0)      { ta = (ln >> 2);       tb = (ln & 3); }
        else if (wi == 1) { ta = 8 + (ln >> 2);   tb = (ln & 3); }
        else if (wi == 2) { ta = 4 + (ln >> 2);   tb = 4 + (ln & 3); }
        else if (wi == 3) {
            if (ln < 16)  { ta = 12 + (ln >> 2);  tb = 4 + (ln & 3); }
            else { int lm = ln - 16; ta = 12 + (lm >> 2); tb = 12 + (lm & 3); }
        } else            { ta = 8 + (ln >> 2);   tb = 8 + (ln & 3); }
    }
    int ti = ta << 2, tj = tb << 2;

    HBAR();

    float mu = 0.f;
    for (int iter = 0; iter < NITER; iter++) {
        if (iter > 0) {
            float alpha = 0.99f * fminf(1.f, min8(red + 16));
            if (t < MDIM) {
                s_ = fmaxf(s_ + alpha * ds_, 1e-30f);
                l_ = fmaxf(l_ + alpha * dl_, 1e-30f);
                rp_ *= (1.f - alpha);
            }
            if (t < CDIM) zv[t] += alpha * dzv[t];
        }
        float cand = 0.f;
        if (t < MDIM) {
            sl_ = s_ * l_;
            dv[t] = l_ / s_;
            cand = sl_;
        }
        cand = warp_rsum(cand);
        if (lane == 0) red[w] = cand;
        HBAR();

        mu = SIGMA * (1.f / MDIM) *
             (red[0] + red[1] + red[2] + red[3] + red[4] + red[5] + red[6] + red[7]);
        if (t < MDIM) {
            float wv = (mu - sl_ + l_ * rp_) / s_;
            lwv[t] = l_ + wv;
        }
        HBAR();

        float a16[16];
        if (tact) {
            ull accA[4], accB[4];
            {
                float4 q0 = *(const float4*)&g_Q[(ti + 0) * CDIM + tj];
                float4 q1 = *(const float4*)&g_Q[(ti + 1) * CDIM + tj];
                float4 q2 = *(const float4*)&g_Q[(ti + 2) * CDIM + tj];
                float4 q3 = *(const float4*)&g_Q[(ti + 3) * CDIM + tj];
                accA[0] = f2pack(q0.x, q1.x); accA[1] = f2pack(q0.y, q1.y);
                accA[2] = f2pack(q0.z, q1.z); accA[3] = f2pack(q0.w, q1.w);
                accB[0] = f2pack(q2.x, q3.x); accB[1] = f2pack(q2.y, q3.y);
                accB[2] = f2pack(q2.z, q3.z); accB[3] = f2pack(q2.w, q3.w);
            }
#pragma unroll 2
            for (int m = 0; m < MDIM; m++) {
                const float* gr = Gp + m * GS;
                ull dm2 = f2dup(dv[m]);
                float2 fa01 = *(const float2*)(gr + ti);
                float2 fa23 = *(const float2*)(gr + ti + 2);
                float2 fb01 = *(const float2*)(gr + tj);
                float2 fb23 = *(const float2*)(gr + tj + 2);
                ull sa01 = f2mul(f2pack(fa01.x, fa01.y), dm2);
                ull sa23 = f2mul(f2pack(fa23.x, fa23.y), dm2);
                ull db0 = f2dup(fb01.x), db1 = f2dup(fb01.y);
                ull db2 = f2dup(fb23.x), db3 = f2dup(fb23.y);
                accA[0] = f2fma(sa01, db0, accA[0]);
                accA[1] = f2fma(sa01, db1, accA[1]);
                accA[2] = f2fma(sa01, db2, accA[2]);
                accA[3] = f2fma(sa01, db3, accA[3]);
                accB[0] = f2fma(sa23, db0, accB[0]);
                accB[1] = f2fma(sa23, db1, accB[1]);
                accB[2] = f2fma(sa23, db2, accB[2]);
                accB[3] = f2fma(sa23, db3, accB[3]);
            }
#pragma unroll
            for (int c = 0; c < 4; c++) {
                f2unpack(accA[c], a16[0 * 4 + c], a16[1 * 4 + c]);
                f2unpack(accB[c], a16[2 * 4 + c], a16[3 * 4 + c]);
            }
            if (t == 0) diag_ldl(a16, 0, LbD, Lc, invDall);
        } else if (t >= 160 && t < 160 + CDIM) {
            int c = t - 160;
            float acc = pb[c] + dot64_f2(zv, &g_Q[c * CDIM]);
#pragma unroll 4
            for (int m = 0; m < MDIM; m++) acc += lwv[m] * Gp[m * GS + c];
            yv[c] = -acc;
        }
        HBAR();

        for (int jb = 0; jb < 16; jb++) {
            int cb = jb << 2;
            if (tact && tb == jb && ta > jb) {
#pragma unroll
                for (int c = 0; c < 4; c++) {
                    float inv = invDall[cb + c];
                    float l0 = LbD[c * 4 + 0];
                    float l1 = LbD[c * 4 + 1];
                    float l2 = LbD[c * 4 + 2];
#pragma unroll
                    for (int r = 0; r < 4; r++) {
                        float x = a16[r * 4 + c];
                        if (c > 0) x -= a16[r * 4 + 0] * l0;
                        if (c > 1) x -= a16[r * 4 + 1] * l1;
                        if (c > 2) x -= a16[r * 4 + 2] * l2;
                        a16[r * 4 + c] = x;
                        float l = x * inv;
                        Xb[(ti + r) * 4 + c] = x;
                        Lb[(ti + r) * 4 + c] = l;
                        Lc[(cb + c) * LCS + (ti + r)] = l;
                    }
                }
            } else if (t == 224) {
#pragma unroll
                for (int c = 0; c < 4; c++) {
                    float yc = yv[cb + c];
#pragma unroll
                    for (int k = 0; k < 4; k++)
                        if (k < c) yc -= LbD[c * 4 + k] * yv[cb + k];
                    yv[cb + c] = yc;
                }
            }
            HBAR();
            if (jb < 15) {
                if (tact && ta > jb && tb > jb) {
                    const float4* X4 = (const float4*)Xb;
                    const float4* L4 = (const float4*)Lb;
                    float4 xr0 = X4[ti + 0], xr1 = X4[ti + 1],
                           xr2 = X4[ti + 2], xr3 = X4[ti + 3];
                    float4 lc0 = L4[tj + 0], lc1 = L4[tj + 1],
                           lc2 = L4[tj + 2], lc3 = L4[tj + 3];
#define DOT4(p, q) (p.x * q.x + p.y * q.y + p.z * q.z + p.w * q.w)
                    a16[0]  -= DOT4(xr0, lc0); a16[1]  -= DOT4(xr0, lc1);
                    a16[2]  -= DOT4(xr0, lc2); a16[3]  -= DOT4(xr0, lc3);
                    a16[4]  -= DOT4(xr1, lc0); a16[5]  -= DOT4(xr1, lc1);
                    a16[6]  -= DOT4(xr1, lc2); a16[7]  -= DOT4(xr1, lc3);
                    a16[8]  -= DOT4(xr2, lc0); a16[9]  -= DOT4(xr2, lc1);
                    a16[10] -= DOT4(xr2, lc2); a16[11] -= DOT4(xr2, lc3);
                    a16[12] -= DOT4(xr3, lc0); a16[13] -= DOT4(xr3, lc1);
                    a16[14] -= DOT4(xr3, lc2); a16[15] -= DOT4(xr3, lc3);
#undef DOT4
                    if (ta == jb + 1 && tb == jb + 1)
                        diag_ldl(a16, cb + 4, LbD, Lc, invDall);
                } else if (t >= 225 && t < 225 + (15 - jb)) {
                    int g = jb + 1 + (t - 225);
                    int r0 = g << 2;
                    float y0 = yv[cb + 0], y1 = yv[cb + 1],
                          y2 = yv[cb + 2], y3 = yv[cb + 3];
                    const float4* L4 = (const float4*)Lb;
#pragma unroll
                    for (int r = 0; r < 4; r++) {
                        float4 lr = L4[r0 + r];
                        yv[r0 + r] -= lr.x * y0 + lr.y * y1 + lr.z * y2 + lr.w * y3;
                    }
                }
                HBAR();
            }
        }

        if (w == 0) {
            float w0 = yv[lane] * invDall[lane];
            float w1 = yv[lane + 32] * invDall[lane + 32];
            for (int j = CDIM - 1; j >= 0; j--) {
                float src = (j >= 32) ? w1 : w0;
                float xj = __shfl_sync(0xffffffffu, src, j & 31);
                xj = scrub(xj);
                if (lane == (j & 31)) dzv[j] = xj;
                if (lane < j)      w0 -= Lc[lane * LCS + j] * xj;
                if (lane + 32 < j) w1 -= Lc[(lane + 32) * LCS + j] * xj;
            }
        }
        HBAR();

        float ac = CLAMP_BIG;
        if (t < MDIM) {
            float acc = -rp_ - dot64_f2(dzv, Gp + t * GS);
            ds_ = scrub(acc);
            dl_ = scrub((mu - sl_ - l_ * ds_) / s_);
            float x1 = (ds_ < 0.f) ? (-s_ / ds_) : CLAMP_BIG;
            float x2 = (dl_ < 0.f) ? (-l_ / dl_) : CLAMP_BIG;
            ac = fminf(x1, x2);
        }
        ac = warp_rmin(ac);
        if (lane == 0) red[16 + w] = ac;
        HBAR();
    }

    float alphaF = 0.99f * fminf(1.f, min8(red + 16));
    float zf = (t < CDIM) ? (zv[t] + alphaF * dzv[t]) : -CLAMP_BIG;

    float mz = warp_rmax(zf);
    if (lane == 0) red[w] = mz;
    HBAR();
    float zmax = fmaxf(fmaxf(fmaxf(red[0], red[1]), fmaxf(red[2], red[3])),
                       fmaxf(fmaxf(red[4], red[5]), fmaxf(red[6], red[7])));
    float ev = (t < CDIM) ? expf(zf - zmax) : 0.f;
    ev = warp_rsum(ev);
    if (lane == 0) red[8 + w] = ev;
    HBAR();
    float ssum = red[8] + red[9] + red[10] + red[11] +
                 red[12] + red[13] + red[14] + red[15];
    float lse = logf(ssum);
    if (t < CDIM)
        out[(size_t)b * CDIM + t] = zf - zmax - lse;
#undef HBAR
}

extern "C" void kernel_launch(void* const* d_in, const int* in_sizes, int n_in,
                              void* d_out, int out_size)
{
    const float* x    = (const float*)d_in[0];
    const float* W1   = (const float*)d_in[1];
    const float* b1   = (const float*)d_in[2];
    const float* W2   = (const float*)d_in[3];
    const float* b2   = (const float*)d_in[4];
    const float* bn1g = (const float*)d_in[5];
    const float* bn1b = (const float*)d_in[6];
    const float* bn2g = (const float*)d_in[7];
    const float* bn2b = (const float*)d_in[8];
    const float* L    = (const float*)d_in[9];
    const float* G    = (const float*)d_in[10];
    const float* z0   = (const float*)d_in[11];
    const float* s0   = (const float*)d_in[12];
    float* out = (float*)d_out;

    cudaFuncSetAttribute(ipm_kernel, cudaFuncAttributeMaxDynamicSharedMemorySize,
                         SM_FLOATS * sizeof(float));

    gemm1_kernel<<<dim3(HDIM / 64, BATCH / 64), 256>>>(x, W1, b1);
    bn1_prep_kernel<<<17, 256>>>(bn1g, bn1b, L, G, z0, s0);
    gemm2_kernel<<<BATCH / 64, 256>>>(W2, b2);
    ipm_kernel<<<BATCH / 2, 512, SM_FLOATS * sizeof(float)>>>(G, bn2g, bn2b, out);
}

// round 14
// speedup vs baseline: 1.1630x; 1.0440x over previous
#include <cuda_runtime.h>
#include <math.h>

#define BATCH 2048
#define FDIM  1024
#define HDIM  1024
#define CDIM  64
#define MDIM  200
#define NITER 20
#define SIGMA 0.1f
#define EPSQP 1e-4f
#define BNEPS 1e-5f
#define CLAMP_BIG 1e30f

__device__ float g_y1[BATCH * HDIM];
__device__ float g_pp[BATCH * CDIM];
__device__ float g_a1[HDIM];
__device__ float g_c1[HDIM];
__device__ float g_Q[CDIM * CDIM];
__device__ float g_h[MDIM];
__device__ float g_part1[32 * CDIM];
__device__ float g_part2[32 * CDIM];

typedef unsigned long long ull;
__device__ __forceinline__ ull f2dup(float s) {
    ull r; asm("mov.b64 %0, {%1, %1};" : "=l"(r) : "f"(s)); return r;
}
__device__ __forceinline__ ull f2pack(float lo, float hi) {
    ull r; asm("mov.b64 %0, {%1, %2};" : "=l"(r) : "f"(lo), "f"(hi)); return r;
}
__device__ __forceinline__ ull f2mul(ull a, ull b) {
    ull d; asm("mul.rn.f32x2 %0, %1, %2;" : "=l"(d) : "l"(a), "l"(b)); return d;
}
__device__ __forceinline__ ull f2fma(ull a, ull b, ull c) {
    ull d; asm("fma.rn.f32x2 %0, %1, %2, %3;" : "=l"(d) : "l"(a), "l"(b), "l"(c)); return d;
}
__device__ __forceinline__ void f2unpack(ull v, float& lo, float& hi) {
    asm("mov.b64 {%0, %1}, %2;" : "=f"(lo), "=f"(hi) : "l"(v));
}

// ---------------- GEMM1 ----------------
__global__ void __launch_bounds__(256) gemm1_kernel(const float* __restrict__ x,
                                                    const float* __restrict__ W1,
                                                    const float* __restrict__ b1)
{
    __shared__ float As[16][64];
    __shared__ float Bs[16][64];
    int tid = threadIdx.x;
    int hb = blockIdx.x * 64, rb = blockIdx.y * 64;
    int lr = tid >> 2, lk = (tid & 3) << 2;
    int ty = tid >> 4, tx = tid & 15;
    float acc[4][4];
#pragma unroll
    for (int u = 0; u < 4; u++)
#pragma unroll
        for (int v = 0; v < 4; v++) acc[u][v] = 0.f;

    const float* xp = x + (size_t)(rb + lr) * FDIM + lk;
    const float* wp = W1 + (size_t)(hb + lr) * FDIM + lk;

    for (int k0 = 0; k0 < FDIM; k0 += 16) {
        float4 av = *(const float4*)(xp + k0);
        float4 bv = *(const float4*)(wp + k0);
        As[lk + 0][lr] = av.x; As[lk + 1][lr] = av.y; As[lk + 2][lr] = av.z; As[lk + 3][lr] = av.w;
        Bs[lk + 0][lr] = bv.x; Bs[lk + 1][lr] = bv.y; Bs[lk + 2][lr] = bv.z; Bs[lk + 3][lr] = bv.w;
        __syncthreads();
#pragma unroll
        for (int k = 0; k < 16; k++) {
            float4 a4 = *(const float4*)&As[k][ty << 2];
            float4 b4 = *(const float4*)&Bs[k][tx << 2];
            float a_[4] = {a4.x, a4.y, a4.z, a4.w};
            float b_[4] = {b4.x, b4.y, b4.z, b4.w};
#pragma unroll
            for (int u = 0; u < 4; u++)
#pragma unroll
                for (int v = 0; v < 4; v++) acc[u][v] += a_[u] * b_[v];
        }
        __syncthreads();
    }
#pragma unroll
    for (int u = 0; u < 4; u++) {
        int r = rb + (ty << 2) + u;
        int h = hb + (tx << 2);
        float4 o;
        o.x = fmaxf(acc[u][0] + b1[h + 0], 0.f);
        o.y = fmaxf(acc[u][1] + b1[h + 1], 0.f);
        o.z = fmaxf(acc[u][2] + b1[h + 2], 0.f);
        o.w = fmaxf(acc[u][3] + b1[h + 3], 0.f);
        *(float4*)&g_y1[(size_t)r * HDIM + h] = o;
    }
}

// ---------------- BN1 stats (blocks 0-15) + prep (block 16) ----------------
__global__ void bn1_prep_kernel(const float* __restrict__ gamma, const float* __restrict__ beta,
                                const float* __restrict__ L, const float* __restrict__ G,
                                const float* __restrict__ z0, const float* __restrict__ s0)
{
    int tid = threadIdx.x;
    if (blockIdx.x == 16) {
        for (int idx = tid; idx < CDIM * CDIM; idx += 256) {
            int i = idx >> 6, j = idx & 63;
            int km = i < j ? i : j;
            float acc = (i == j) ? EPSQP : 0.f;
            for (int k = 0; k <= km; k++) acc += L[i * CDIM + k] * L[j * CDIM + k];
            g_Q[idx] = acc;
        }
        for (int m = tid; m < MDIM; m += 256) {
            float acc = s0[m];
            for (int i = 0; i < CDIM; i++) acc += G[m * CDIM + i] * z0[i];
            g_h[m] = acc;
        }
        return;
    }
    __shared__ float s1[256], s2[256];
    int colBase = blockIdx.x * 64;
    int col = colBase + (tid & 63);
    int rs = tid >> 6;
    float sum = 0.f, sq = 0.f;
    for (int r = rs; r < BATCH; r += 4) {
        float v = g_y1[(size_t)r * HDIM + col];
        sum += v; sq += v * v;
    }
    s1[tid] = sum; s2[tid] = sq;
    __syncthreads();
    if (tid < 64) {
        float S = s1[tid] + s1[tid + 64] + s1[tid + 128] + s1[tid + 192];
        float P = s2[tid] + s2[tid + 64] + s2[tid + 128] + s2[tid + 192];
        float mean = S * (1.f / BATCH);
        float var = P * (1.f / BATCH) - mean * mean;
        float a = gamma[colBase + tid] / sqrtf(var + BNEPS);
        g_a1[colBase + tid] = a;
        g_c1[colBase + tid] = beta[colBase + tid] - mean * a;
    }
}

// ---------------- GEMM2 + bn2 per-block partial sums ----------------
__global__ void __launch_bounds__(256) gemm2_kernel(const float* __restrict__ W2,
                                                    const float* __restrict__ b2)
{
    __shared__ float As[16][64];
    __shared__ float Bs[16][64];
    __shared__ float a1s[HDIM];
    __shared__ float c1s[HDIM];
    int tid = threadIdx.x;
    for (int i = tid; i < HDIM; i += 256) { a1s[i] = g_a1[i]; c1s[i] = g_c1[i]; }
    __syncthreads();

    int rb = blockIdx.x * 64;
    int lr = tid >> 2, lk = (tid & 3) << 2;
    int ty = tid >> 4, tx = tid & 15;
    float acc[4][4];
#pragma unroll
    for (int u = 0; u < 4; u++)
#pragma unroll
        for (int v = 0; v < 4; v++) acc[u][v] = 0.f;

    const float* yp = g_y1 + (size_t)(rb + lr) * HDIM + lk;
    const float* wp = W2 + (size_t)lr * HDIM + lk;

    for (int k0 = 0; k0 < HDIM; k0 += 16) {
        float4 av = *(const float4*)(yp + k0);
        float4 bv = *(const float4*)(wp + k0);
        As[lk + 0][lr] = av.x * a1s[k0 + lk + 0] + c1s[k0 + lk + 0];
        As[lk + 1][lr] = av.y * a1s[k0 + lk + 1] + c1s[k0 + lk + 1];
        As[lk + 2][lr] = av.z * a1s[k0 + lk + 2] + c1s[k0 + lk + 2];
        As[lk + 3][lr] = av.w * a1s[k0 + lk + 3] + c1s[k0 + lk + 3];
        Bs[lk + 0][lr] = bv.x; Bs[lk + 1][lr] = bv.y; Bs[lk + 2][lr] = bv.z; Bs[lk + 3][lr] = bv.w;
        __syncthreads();
#pragma unroll
        for (int k = 0; k < 16; k++) {
            float4 a4 = *(const float4*)&As[k][ty << 2];
            float4 b4 = *(const float4*)&Bs[k][tx << 2];
            float a_[4] = {a4.x, a4.y, a4.z, a4.w};
            float b_[4] = {b4.x, b4.y, b4.z, b4.w};
#pragma unroll
            for (int u = 0; u < 4; u++)
#pragma unroll
                for (int v = 0; v < 4; v++) acc[u][v] += a_[u] * b_[v];
        }
        __syncthreads();
    }
    float cs[4] = {0.f, 0.f, 0.f, 0.f};
    float cq[4] = {0.f, 0.f, 0.f, 0.f};
#pragma unroll
    for (int u = 0; u < 4; u++) {
        int r = rb + (ty << 2) + u;
        int n = tx << 2;
        float4 o;
        o.x = fmaxf(acc[u][0] + b2[n + 0], 0.f);
        o.y = fmaxf(acc[u][1] + b2[n + 1], 0.f);
        o.z = fmaxf(acc[u][2] + b2[n + 2], 0.f);
        o.w = fmaxf(acc[u][3] + b2[n + 3], 0.f);
        cs[0] += o.x; cq[0] += o.x * o.x;
        cs[1] += o.y; cq[1] += o.y * o.y;
        cs[2] += o.z; cq[2] += o.z * o.z;
        cs[3] += o.w; cq[3] += o.w * o.w;
        *(float4*)&g_pp[(size_t)r * CDIM + n] = o;
    }
    __syncthreads();
#pragma unroll
    for (int v = 0; v < 4; v++) { As[ty][(tx << 2) + v] = cs[v]; Bs[ty][(tx << 2) + v] = cq[v]; }
    __syncthreads();
    if (tid < 64) {
        float S = 0.f, P = 0.f;
#pragma unroll
        for (int g = 0; g < 16; g++) { S += As[g][tid]; P += Bs[g][tid]; }
        g_part1[blockIdx.x * CDIM + tid] = S;
        g_part2[blockIdx.x * CDIM + tid] = P;
    }
}

// ---------------- IPM ----------------
#define GS 68            // 16B-aligned rows -> LDS.128, conflict-free in 8-lane phases
#define LCS 66
#define SH_FLOATS   (MDIM * GS + 200)
#define HALF_FLOATS (4224 + 256 + 256 + 16 + 5*64 + 2*200 + 40)
#define SM_FLOATS   (SH_FLOATS + 2 * HALF_FLOATS)

__device__ __forceinline__ float scrub(float v)
{
    return fminf(fmaxf(v, -CLAMP_BIG), CLAMP_BIG);
}
__device__ __forceinline__ float warp_rsum(float v)
{
#pragma unroll
    for (int s = 16; s > 0; s >>= 1) v += __shfl_xor_sync(0xffffffffu, v, s);
    return v;
}
__device__ __forceinline__ float warp_rmin(float v)
{
#pragma unroll
    for (int s = 16; s > 0; s >>= 1) v = fminf(v, __shfl_xor_sync(0xffffffffu, v, s));
    return v;
}
__device__ __forceinline__ float warp_rmax(float v)
{
#pragma unroll
    for (int s = 16; s > 0; s >>= 1) v = fmaxf(v, __shfl_xor_sync(0xffffffffu, v, s));
    return v;
}
// float4-based 64-dot: both pointers 16B-aligned; 2 independent f32x2 chains
__device__ __forceinline__ float dot64_f4(const float* a, const float* b)
{
    ull acc0 = 0ull, acc1 = 0ull;
#pragma unroll
    for (int i = 0; i < CDIM; i += 4) {
        float4 x = *(const float4*)(a + i);
        float4 y = *(const float4*)(b + i);
        acc0 = f2fma(f2pack(x.x, x.y), f2pack(y.x, y.y), acc0);
        acc1 = f2fma(f2pack(x.z, x.w), f2pack(y.z, y.w), acc1);
    }
    float l0, h0, l1, h1;
    f2unpack(acc0, l0, h0); f2unpack(acc1, l1, h1);
    return (l0 + h0) + (l1 + h1);
}
__device__ __forceinline__ float min8(const float* red)
{
    return fminf(fminf(fminf(red[0], red[1]), fminf(red[2], red[3])),
                 fminf(fminf(red[4], red[5]), fminf(red[6], red[7])));
}

__device__ __forceinline__ void diag_ldl(float* a16, int cb, float* LbD,
                                         float* Lc, float* invDall)
{
#pragma unroll
    for (int c = 0; c < 4; c++) {
        float h0 = a16[c * 4 + c];
        float v = h0;
#pragma unroll
        for (int k = 0; k < 4; k++)
            if (k < c) v -= a16[c * 4 + k] * LbD[c * 4 + k];
        float piv = fmaxf(v, 1e-12f * fmaxf(h0, EPSQP));
        float inv = 1.f / piv;
        invDall[cb + c] = inv;
#pragma unroll
        for (int r = 0; r < 4; r++) {
            if (r > c) {
                float x = a16[r * 4 + c];
#pragma unroll
                for (int k = 0; k < 4; k++)
                    if (k < c) x -= a16[r * 4 + k] * LbD[c * 4 + k];
                a16[r * 4 + c] = x;
                float l = x * inv;
                LbD[r * 4 + c] = l;
                Lc[(cb + c) * LCS + (cb + r)] = l;
            }
        }
    }
}

__global__ void __launch_bounds__(512, 2) ipm_kernel(const float* __restrict__ G,
                                                     const float* __restrict__ bn2g,
                                                     const float* __restrict__ bn2b,
                                                     float* __restrict__ out)
{
    extern __shared__ float sm[];
    float* Gp = sm;
    float* hh = Gp + MDIM * GS;
    int tid  = threadIdx.x;
    int half = tid >> 8;
    int t    = tid & 255;
    int barid = 1 + half;

    float* ms      = hh + 200 + half * HALF_FLOATS;
    float* Lc      = ms;
    float* Xb      = Lc + 4224;
    float* Lb      = Xb + 256;
    float* LbD     = Lb + 256;
    float* invDall = LbD + 16;
    float* yv      = invDall + 64;
    float* dzv     = yv + 64;
    float* pb      = dzv + 64;
    float* zv      = pb + 64;
    float* dv      = zv + 64;
    float* lwv     = dv + 200;
    float* red     = lwv + 200;

#define HBAR() asm volatile("bar.sync %0, %1;" :: "r"(barid), "r"(256) : "memory")

    int b = blockIdx.x * 2 + half;
    int w = t >> 5;
    int lane = t & 31;

    for (int idx = tid; idx < MDIM * CDIM; idx += 512) {
        int m = idx >> 6, i = idx & 63;
        Gp[m * GS + i] = G[idx];
    }
    if (tid < MDIM) hh[tid] = g_h[tid];
    __syncthreads();

    float s_ = 1.f, l_ = 1.f, sl_ = 1.f;
    float rp_ = (t < MDIM) ? (1.f - hh[t]) : 0.f;
    float ds_ = 0.f, dl_ = 0.f;

    if (t < CDIM) {
        float S = 0.f, P = 0.f;
#pragma unroll 4
        for (int blk = 0; blk < 32; blk++) {
            S += __ldg(&g_part1[blk * CDIM + t]);
            P += __ldg(&g_part2[blk * CDIM + t]);
        }
        float mean = S * (1.f / BATCH);
        float var = P * (1.f / BATCH) - mean * mean;
        float a2 = bn2g[t] / sqrtf(var + BNEPS);
        float c2 = bn2b[t] - mean * a2;
        pb[t] = a2 * g_pp[(size_t)b * CDIM + t] + c2;
        zv[t] = 0.f;
    }

    bool tact = false;
    int ta = 0, tb = 0;
    if (t < 160) {
        int wi = t >> 5, ln = t & 31;
        tact = true;
        if (wi == 0)      { ta = (ln >> 2);       tb = (ln & 3); }
        else if (wi == 1) { ta = 8 + (ln >> 2);   tb = (ln & 3); }
        else if (wi == 2) { ta = 4 + (ln >> 2);   tb = 4 + (ln & 3); }
        else if (wi == 3) {
            if (ln < 16)  { ta = 12 + (ln >> 2);  tb = 4 + (ln & 3); }
            else { int lm = ln - 16; ta = 12 + (lm >> 2); tb = 12 + (lm & 3); }
        } else            { ta = 8 + (ln >> 2);   tb = 8 + (ln & 3); }
    }
    int ti = ta << 2, tj = tb << 2;

    HBAR();

    float mu = 0.f;
    for (int iter = 0; iter < NITER; iter++) {
        if (iter > 0) {
            float alpha = 0.99f * fminf(1.f, min8(red + 16));
            if (t < MDIM) {
                s_ = fmaxf(s_ + alpha * ds_, 1e-30f);
                l_ = fmaxf(l_ + alpha * dl_, 1e-30f);
                rp_ *= (1.f - alpha);
            }
            if (t < CDIM) zv[t] += alpha * dzv[t];
        }
        float cand = 0.f;
        if (t < MDIM) {
            sl_ = s_ * l_;
            dv[t] = l_ / s_;
            cand = sl_;
        }
        cand = warp_rsum(cand);
        if (lane == 0) red[w] = cand;
        HBAR();

        mu = SIGMA * (1.f / MDIM) *
             (red[0] + red[1] + red[2] + red[3] + red[4] + red[5] + red[6] + red[7]);
        if (t < MDIM) {
            float wv = (mu - sl_ + l_ * rp_) / s_;
            lwv[t] = l_ + wv;
        }
        HBAR();

        float a16[16];
        if (tact) {
            ull accA[4], accB[4];
            {
                float4 q0 = *(const float4*)&g_Q[(ti + 0) * CDIM + tj];
                float4 q1 = *(const float4*)&g_Q[(ti + 1) * CDIM + tj];
                float4 q2 = *(const float4*)&g_Q[(ti + 2) * CDIM + tj];
                float4 q3 = *(const float4*)&g_Q[(ti + 3) * CDIM + tj];
                accA[0] = f2pack(q0.x, q1.x); accA[1] = f2pack(q0.y, q1.y);
                accA[2] = f2pack(q0.z, q1.z); accA[3] = f2pack(q0.w, q1.w);
                accB[0] = f2pack(q2.x, q3.x); accB[1] = f2pack(q2.y, q3.y);
                accB[2] = f2pack(q2.z, q3.z); accB[3] = f2pack(q2.w, q3.w);
            }
#pragma unroll 2
            for (int m = 0; m < MDIM; m++) {
                const float* gr = Gp + m * GS;
                ull dm2 = f2dup(dv[m]);
                float4 fa = *(const float4*)(gr + ti);   // LDS.128
                float4 fb = *(const float4*)(gr + tj);   // LDS.128
                ull sa01 = f2mul(f2pack(fa.x, fa.y), dm2);
                ull sa23 = f2mul(f2pack(fa.z, fa.w), dm2);
                ull db0 = f2dup(fb.x), db1 = f2dup(fb.y);
                ull db2 = f2dup(fb.z), db3 = f2dup(fb.w);
                accA[0] = f2fma(sa01, db0, accA[0]);
                accA[1] = f2fma(sa01, db1, accA[1]);
                accA[2] = f2fma(sa01, db2, accA[2]);
                accA[3] = f2fma(sa01, db3, accA[3]);
                accB[0] = f2fma(sa23, db0, accB[0]);
                accB[1] = f2fma(sa23, db1, accB[1]);
                accB[2] = f2fma(sa23, db2, accB[2]);
                accB[3] = f2fma(sa23, db3, accB[3]);
            }
#pragma unroll
            for (int c = 0; c < 4; c++) {
                f2unpack(accA[c], a16[0 * 4 + c], a16[1 * 4 + c]);
                f2unpack(accB[c], a16[2 * 4 + c], a16[3 * 4 + c]);
            }
            if (t == 0) diag_ldl(a16, 0, LbD, Lc, invDall);
        } else if (t >= 160 && t < 160 + CDIM) {
            int c = t - 160;
            float acc = pb[c] + dot64_f4(zv, &g_Q[c * CDIM]);
#pragma unroll 4
            for (int m = 0; m < MDIM; m++) acc += lwv[m] * Gp[m * GS + c];
            yv[c] = -acc;
        }
        HBAR();

        for (int jb = 0; jb < 16; jb++) {
            int cb = jb << 2;
            if (tact && tb == jb && ta > jb) {
#pragma unroll
                for (int c = 0; c < 4; c++) {
                    float inv = invDall[cb + c];
                    float l0 = LbD[c * 4 + 0];
                    float l1 = LbD[c * 4 + 1];
                    float l2 = LbD[c * 4 + 2];
#pragma unroll
                    for (int r = 0; r < 4; r++) {
                        float x = a16[r * 4 + c];
                        if (c > 0) x -= a16[r * 4 + 0] * l0;
                        if (c > 1) x -= a16[r * 4 + 1] * l1;
                        if (c > 2) x -= a16[r * 4 + 2] * l2;
                        a16[r * 4 + c] = x;
                        float l = x * inv;
                        Xb[(ti + r) * 4 + c] = x;
                        Lb[(ti + r) * 4 + c] = l;
                        Lc[(cb + c) * LCS + (ti + r)] = l;
                    }
                }
            } else if (t == 224) {
#pragma unroll
                for (int c = 0; c < 4; c++) {
                    float yc = yv[cb + c];
#pragma unroll
                    for (int k = 0; k < 4; k++)
                        if (k < c) yc -= LbD[c * 4 + k] * yv[cb + k];
                    yv[cb + c] = yc;
                }
            }
            HBAR();
            if (jb < 15) {
                if (tact && ta > jb && tb > jb) {
                    const float4* X4 = (const float4*)Xb;
                    const float4* L4 = (const float4*)Lb;
                    float4 xr0 = X4[ti + 0], xr1 = X4[ti + 1],
                           xr2 = X4[ti + 2], xr3 = X4[ti + 3];
                    float4 lc0 = L4[tj + 0], lc1 = L4[tj + 1],
                           lc2 = L4[tj + 2], lc3 = L4[tj + 3];
#define DOT4(p, q) (p.x * q.x + p.y * q.y + p.z * q.z + p.w * q.w)
                    a16[0]  -= DOT4(xr0, lc0); a16[1]  -= DOT4(xr0, lc1);
                    a16[2]  -= DOT4(xr0, lc2); a16[3]  -= DOT4(xr0, lc3);
                    a16[4]  -= DOT4(xr1, lc0); a16[5]  -= DOT4(xr1, lc1);
                    a16[6]  -= DOT4(xr1, lc2); a16[7]  -= DOT4(xr1, lc3);
                    a16[8]  -= DOT4(xr2, lc0); a16[9]  -= DOT4(xr2, lc1);
                    a16[10] -= DOT4(xr2, lc2); a16[11] -= DOT4(xr2, lc3);
                    a16[12] -= DOT4(xr3, lc0); a16[13] -= DOT4(xr3, lc1);
                    a16[14] -= DOT4(xr3, lc2); a16[15] -= DOT4(xr3, lc3);
#undef DOT4
                    if (ta == jb + 1 && tb == jb + 1)
                        diag_ldl(a16, cb + 4, LbD, Lc, invDall);
                } else if (t >= 225 && t < 225 + (15 - jb)) {
                    int g = jb + 1 + (t - 225);
                    int r0 = g << 2;
                    float y0 = yv[cb + 0], y1 = yv[cb + 1],
                          y2 = yv[cb + 2], y3 = yv[cb + 3];
                    const float4* L4 = (const float4*)Lb;
#pragma unroll
                    for (int r = 0; r < 4; r++) {
                        float4 lr = L4[r0 + r];
                        yv[r0 + r] -= lr.x * y0 + lr.y * y1 + lr.z * y2 + lr.w * y3;
                    }
                }
                HBAR();
            }
        }

        if (w == 0) {
            float w0 = yv[lane] * invDall[lane];
            float w1 = yv[lane + 32] * invDall[lane + 32];
            for (int j = CDIM - 1; j >= 0; j--) {
                float src = (j >= 32) ? w1 : w0;
                float xj = __shfl_sync(0xffffffffu, src, j & 31);
                xj = scrub(xj);
                if (lane == (j & 31)) dzv[j] = xj;
                if (lane < j)      w0 -= Lc[lane * LCS + j] * xj;
                if (lane + 32 < j) w1 -= Lc[(lane + 32) * LCS + j] * xj;
            }
        }
        HBAR();

        float ac = CLAMP_BIG;
        if (t < MDIM) {
            float acc = -rp_ - dot64_f4(dzv, Gp + t * GS);
            ds_ = scrub(acc);
            dl_ = scrub((mu - sl_ - l_ * ds_) / s_);
            float x1 = (ds_ < 0.f) ? (-s_ / ds_) : CLAMP_BIG;
            float x2 = (dl_ < 0.f) ? (-l_ / dl_) : CLAMP_BIG;
            ac = fminf(x1, x2);
        }
        ac = warp_rmin(ac);
        if (lane == 0) red[16 + w] = ac;
        HBAR();
    }

    float alphaF = 0.99f * fminf(1.f, min8(red + 16));
    float zf = (t < CDIM) ? (zv[t] + alphaF * dzv[t]) : -CLAMP_BIG;

    float mz = warp_rmax(zf);
    if (lane == 0) red[w] = mz;
    HBAR();
    float zmax = fmaxf(fmaxf(fmaxf(red[0], red[1]), fmaxf(red[2], red[3])),
                       fmaxf(fmaxf(red[4], red[5]), fmaxf(red[6], red[7])));
    float ev = (t < CDIM) ? expf(zf - zmax) : 0.f;
    ev = warp_rsum(ev);
    if (lane == 0) red[8 + w] = ev;
    HBAR();
    float ssum = red[8] + red[9] + red[10] + red[11] +
                 red[12] + red[13] + red[14] + red[15];
    float lse = logf(ssum);
    if (t < CDIM)
        out[(size_t)b * CDIM + t] = zf - zmax - lse;
#undef HBAR
}

extern "C" void kernel_launch(void* const* d_in, const int* in_sizes, int n_in,
                              void* d_out, int out_size)
{
    const float* x    = (const float*)d_in[0];
    const float* W1   = (const float*)d_in[1];
    const float* b1   = (const float*)d_in[2];
    const float* W2   = (const float*)d_in[3];
    const float* b2   = (const float*)d_in[4];
    const float* bn1g = (const float*)d_in[5];
    const float* bn1b = (const float*)d_in[6];
    const float* bn2g = (const float*)d_in[7];
    const float* bn2b = (const float*)d_in[8];
    const float* L    = (const float*)d_in[9];
    const float* G    = (const float*)d_in[10];
    const float* z0   = (const float*)d_in[11];
    const float* s0   = (const float*)d_in[12];
    float* out = (float*)d_out;

    cudaFuncSetAttribute(ipm_kernel, cudaFuncAttributeMaxDynamicSharedMemorySize,
                         SM_FLOATS * sizeof(float));

    gemm1_kernel<<<dim3(HDIM / 64, BATCH / 64), 256>>>(x, W1, b1);
    bn1_prep_kernel<<<17, 256>>>(bn1g, bn1b, L, G, z0, s0);
    gemm2_kernel<<<BATCH / 64, 256>>>(W2, b2);
    ipm_kernel<<<BATCH / 2, 512, SM_FLOATS * sizeof(float)>>>(G, bn2g, bn2b, out);
}